// round 9
// baseline (speedup 1.0000x reference)
#include <cuda_runtime.h>
#include <math.h>
#include <stdint.h>

#define NINS   2048
#define TOK    16
#define EMB    512
#define HID    256
#define G4     (4*HID)      // 1024
#define PAR    8
#define LEVELS 16
#define KROWS  (NINS/LEVELS) // 128
#define T_PAD  20

// ---------------- scratch (static device globals; no allocation) ----------------
__device__ float g_Xp[NINS*TOK*G4];      // gate-interleaved token input projections
__device__ float g_H[NINS*HID];
__device__ float g_C[NINS*HID];
__device__ float g_H2[NINS*HID];
__device__ float g_C2[NINS*HID];
__device__ float g_Gx[NINS*G4];          // gate-interleaved
__device__ float g_Hi[NINS*HID];
__device__ float g_Ci[NINS*HID];
__device__ float g_h0[KROWS*HID];
__device__ float g_c0[KROWS*HID];
__device__ float g_WhhTokP[G4*HID];      // gate-interleaved rows, tf32-rounded
__device__ float g_WhhInsP[G4*HID];
__device__ float g_WihTokP[G4*EMB];      // gate-interleaved rows, tf32-rounded
__device__ float g_WihInsP[G4*HID];
__device__ float g_biasTokP[G4];         // permuted bih+bhh
__device__ float g_biasInsP[G4];
__device__ unsigned char g_pval[NINS*PAR];
__device__ int   g_appears[NINS];
__device__ float g_partial[64*HID];
__device__ unsigned int g_bar2;

// ---------------- helpers ----------------
__device__ __forceinline__ uint32_t cvt_tf32(float v) {
    uint32_t r;
    asm("cvt.rna.tf32.f32 %0, %1;" : "=r"(r) : "f"(v));
    return r;
}
__device__ __forceinline__ void mma_tf32(float* c, uint32_t a0, uint32_t a1,
                                         uint32_t a2, uint32_t a3,
                                         uint32_t b0, uint32_t b1) {
    asm("mma.sync.aligned.m16n8k8.row.col.f32.tf32.tf32.f32 "
        "{%0,%1,%2,%3}, {%4,%5,%6,%7}, {%8,%9}, {%0,%1,%2,%3};"
        : "+f"(c[0]), "+f"(c[1]), "+f"(c[2]), "+f"(c[3])
        : "r"(a0), "r"(a1), "r"(a2), "r"(a3), "r"(b0), "r"(b1));
}
__device__ __forceinline__ void cp_async16(void* smem, const void* gmem) {
    uint32_t s = (uint32_t)__cvta_generic_to_shared(smem);
    asm volatile("cp.async.cg.shared.global [%0], [%1], 16;\n" :: "r"(s), "l"(gmem));
}

// ---------------- grid barrier for persistent kernels ----------------
__device__ __forceinline__ void grid_sync(unsigned int* bar, unsigned int target) {
    __threadfence();
    __syncthreads();
    if (threadIdx.x == 0) {
        atomicAdd(bar, 1u);
        while (atomicAdd(bar, 0u) < target) { __nanosleep(32); }
    }
    __syncthreads();
    __threadfence();
}

// ---------------- prep ----------------
__global__ void prep_kernel(const unsigned char* __restrict__ pv_raw,
                            const int* __restrict__ pidx)
{
    __shared__ int s_hi, s_b0;
    __shared__ int s_app[NINS];
    int tid = threadIdx.x;
    if (tid == 0) { g_bar2 = 0u; }
    int hi = 0, b0 = 0;
    for (int i = 256 + tid; i < 4096; i += 256) {
        hi |= pv_raw[4*i+1] | pv_raw[4*i+2] | pv_raw[4*i+3];
        b0 |= pv_raw[4*i+0];
    }
    if (tid == 0) { s_hi = 0; s_b0 = 0; }
    __syncthreads();
    if (hi) atomicOr(&s_hi, 1);
    if (b0) atomicOr(&s_b0, 1);
    __syncthreads();
    int mode = (s_hi == 0) ? 0 : (s_b0 == 0 ? 1 : 2);
    for (int i = tid; i < NINS*PAR; i += 256) {
        unsigned char v;
        if (mode == 0)      v = (((const int*)pv_raw)[i]   != 0);
        else if (mode == 1) v = (((const float*)pv_raw)[i] != 0.0f);
        else                v = (pv_raw[i] != 0);
        g_pval[i] = v;
    }
    for (int i = tid; i < NINS; i += 256) s_app[i] = 0;
    __syncthreads();
    for (int i = tid; i < NINS*PAR; i += 256) {
        if (g_pval[i]) atomicAdd(&s_app[pidx[i]], 1);
    }
    __syncthreads();
    for (int i = tid; i < NINS; i += 256) g_appears[i] = s_app[i];
}

// permute weight rows to gate-interleave + round to tf32 (generic K)
__global__ void permW_kernel(const float* __restrict__ Win, float* __restrict__ Wout, int K)
{
    int np = blockIdx.x;
    int n  = (np & 3) * HID + (np >> 2);
    for (int c = threadIdx.x; c < K; c += 256)
        Wout[(size_t)np * K + c] = __uint_as_float(cvt_tf32(Win[(size_t)n * K + c]));
}

__global__ void permBias_kernel(const float* __restrict__ b1, const float* __restrict__ b2,
                                float* __restrict__ out)
{
    int np = blockIdx.x * 256 + threadIdx.x;
    int n  = (np & 3) * HID + (np >> 2);
    out[np] = b1[n] + b2[n];
}

// ============================================================================
// tile GEMM (mma.sync tf32, single-pass): acc += A[bm:,:K] @ B[bn:,:K]^T
// 128x128 tile, BK=16, 2-stage cp.async, 8 warps (2x4). B pre-rounded tf32.
// ============================================================================
template<int KDIM>
__device__ __forceinline__ void tile_gemm(
    const float* __restrict__ A, const float* __restrict__ B,
    int bm, int bn, float (&acc)[4][4][4], float* As, float* Bs)
{
    const int tid  = threadIdx.x;
    const int lane = tid & 31;
    const int warp = tid >> 5;
    const int wm = (warp >> 2) * 64;
    const int wn = (warp & 3) * 32;
    const int g   = lane >> 2;
    const int tig = lane & 3;
    const int NT = KDIM / 16;

#pragma unroll
    for (int u = 0; u < 2; u++) {
        int idx = u * 256 + tid;
        int r = idx >> 2, c4 = idx & 3;
        cp_async16(As + r * T_PAD + c4 * 4, A + (size_t)(bm + r) * KDIM + c4 * 4);
        cp_async16(Bs + r * T_PAD + c4 * 4, B + (size_t)(bn + r) * KDIM + c4 * 4);
    }
    asm volatile("cp.async.commit_group;\n");

    for (int kt = 0; kt < NT; kt++) {
        int cur = kt & 1;
        if (kt + 1 < NT) {
            int nxt = (kt + 1) & 1;
            const float* Ap = A + (size_t)bm * KDIM + (kt + 1) * 16;
            const float* Bp = B + (size_t)bn * KDIM + (kt + 1) * 16;
#pragma unroll
            for (int u = 0; u < 2; u++) {
                int idx = u * 256 + tid;
                int r = idx >> 2, c4 = idx & 3;
                cp_async16(As + nxt * 128 * T_PAD + r * T_PAD + c4 * 4,
                           Ap + (size_t)r * KDIM + c4 * 4);
                cp_async16(Bs + nxt * 128 * T_PAD + r * T_PAD + c4 * 4,
                           Bp + (size_t)r * KDIM + c4 * 4);
            }
            asm volatile("cp.async.commit_group;\n");
            asm volatile("cp.async.wait_group 1;\n");
        } else {
            asm volatile("cp.async.wait_group 0;\n");
        }
        __syncthreads();

        const float* Asb = As + cur * 128 * T_PAD;
        const float* Bsb = Bs + cur * 128 * T_PAD;
#pragma unroll
        for (int ks = 0; ks < 2; ks++) {
            const int k0 = ks * 8;
            uint32_t bf[4][2];
#pragma unroll
            for (int ni = 0; ni < 4; ni++) {
                bf[ni][0] = __float_as_uint(Bsb[(wn + ni*8 + g) * T_PAD + k0 + tig]);
                bf[ni][1] = __float_as_uint(Bsb[(wn + ni*8 + g) * T_PAD + k0 + tig + 4]);
            }
            uint32_t af[4][4];
#pragma unroll
            for (int mi = 0; mi < 4; mi++) {
                int r0 = (wm + mi*16 + g) * T_PAD + k0;
                int r1 = (wm + mi*16 + 8 + g) * T_PAD + k0;
                af[mi][0] = cvt_tf32(Asb[r0 + tig]);
                af[mi][1] = cvt_tf32(Asb[r1 + tig]);
                af[mi][2] = cvt_tf32(Asb[r0 + tig + 4]);
                af[mi][3] = cvt_tf32(Asb[r1 + tig + 4]);
            }
#pragma unroll
            for (int mi = 0; mi < 4; mi++)
#pragma unroll
                for (int ni = 0; ni < 4; ni++)
                    mma_tf32(acc[mi][ni], af[mi][0], af[mi][1], af[mi][2], af[mi][3],
                             bf[ni][0], bf[ni][1]);
        }
        __syncthreads();
    }
}

// fused LSTM epilogue; Add is gate-interleaved ([row][h*4+gate]) -> one float4
__device__ __forceinline__ void fuse_epilogue(
    float (&acc)[4][4][4], int bm, int bn,
    const float* __restrict__ Add, long addStride,
    const float* __restrict__ Cprev,
    float* __restrict__ Hout, float* __restrict__ Cstate)
{
    const int lane = threadIdx.x & 31;
    const int warp = threadIdx.x >> 5;
    const int wm = (warp >> 2) * 64;
    const int wn = (warp & 3) * 32;
    const int g   = lane >> 2;
    const int tig = lane & 3;
#pragma unroll
    for (int mi = 0; mi < 4; mi++) {
#pragma unroll
        for (int ni = 0; ni < 4; ni++) {
            float c0 = acc[mi][ni][0], c1 = acc[mi][ni][1];
            float c2 = acc[mi][ni][2], c3 = acc[mi][ni][3];
            float x0 = __shfl_xor_sync(0xffffffffu, c0, 1);
            float x1 = __shfl_xor_sync(0xffffffffu, c1, 1);
            float x2 = __shfl_xor_sync(0xffffffffu, c2, 1);
            float x3 = __shfl_xor_sync(0xffffffffu, c3, 1);
            int q = tig >> 1;
            int h = (bn + wn + ni*8 + q*4) >> 2;
            int row;
            float gi, gf, gg, go;
            if ((tig & 1) == 0) {
                row = bm + wm + mi*16 + g;
                gi = c0; gf = c1; gg = x0; go = x1;
            } else {
                row = bm + wm + mi*16 + 8 + g;
                gi = x2; gf = x3; gg = c2; go = c3;
            }
            const float4 ad4 = *(const float4*)(Add + (size_t)row * addStride + 4*h);
            gi += ad4.x;
            gf += ad4.y;
            gg += ad4.z;
            go += ad4.w;
            float c = Cprev ? Cprev[(size_t)row * HID + h] : 0.0f;
            float si = 1.0f / (1.0f + expf(-gi));
            float sf = 1.0f / (1.0f + expf(-gf));
            float so = 1.0f / (1.0f + expf(-go));
            float cn = sf * c + si * tanhf(gg);
            float hn = so * tanhf(cn);
            Cstate[(size_t)row * HID + h] = cn;
            Hout[(size_t)row * HID + h]   = hn;
        }
    }
}

// ============================================================================
// Plain GEMM kernel (phase-1 Xp and phase-3a Gx): C = A@B^T + bias (permuted)
// ============================================================================
template<int KDIM>
__global__ __launch_bounds__(256, 2) void mma_plain_kernel(
    const float* __restrict__ A, const float* __restrict__ B,
    float* __restrict__ Cout, const float* __restrict__ bias)
{
    __shared__ float As[2*128*T_PAD];
    __shared__ float Bs[2*128*T_PAD];
    const int bm = blockIdx.y * 128;
    const int bn = blockIdx.x * 128;
    const int lane = threadIdx.x & 31;
    const int warp = threadIdx.x >> 5;
    const int wm = (warp >> 2) * 64;
    const int wn = (warp & 3) * 32;
    const int g   = lane >> 2;
    const int tig = lane & 3;

    float acc[4][4][4];
#pragma unroll
    for (int mi = 0; mi < 4; mi++)
#pragma unroll
        for (int ni = 0; ni < 4; ni++)
#pragma unroll
            for (int r = 0; r < 4; r++) acc[mi][ni][r] = 0.0f;

    tile_gemm<KDIM>(A, B, bm, bn, acc, As, Bs);

#pragma unroll
    for (int mi = 0; mi < 4; mi++) {
        int r0 = bm + wm + mi*16 + g;
        int r1 = r0 + 8;
#pragma unroll
        for (int ni = 0; ni < 4; ni++) {
            int c = bn + wn + ni*8 + tig*2;
            float bb0 = bias[c];
            float bb1 = bias[c+1];
            float2 v0 = make_float2(acc[mi][ni][0] + bb0, acc[mi][ni][1] + bb1);
            float2 v1 = make_float2(acc[mi][ni][2] + bb0, acc[mi][ni][3] + bb1);
            *(float2*)(Cout + (size_t)r0 * G4 + c) = v0;
            *(float2*)(Cout + (size_t)r1 * G4 + c) = v1;
        }
    }
}

// ============================================================================
// Phase-2 persistent kernel: all 16 token-LSTM steps. 128 blocks.
// ============================================================================
__global__ __launch_bounds__(256, 2) void phase2_kernel()
{
    __shared__ float As[2*128*T_PAD];
    __shared__ float Bs[2*128*T_PAD];
    const int bm = (blockIdx.x >> 3) * 128;
    const int bn = (blockIdx.x & 7) * 128;

    for (int t = 0; t < TOK; t++) {
        float acc[4][4][4];
#pragma unroll
        for (int mi = 0; mi < 4; mi++)
#pragma unroll
            for (int ni = 0; ni < 4; ni++)
#pragma unroll
                for (int r = 0; r < 4; r++) acc[mi][ni][r] = 0.0f;

        const float* Hsrc = (t & 1) ? g_H2 : g_H;
        const float* Csrc = (t & 1) ? g_C2 : g_C;
        float* Hdst = (t & 1) ? g_H : g_H2;
        float* Cdst = (t & 1) ? g_C : g_C2;

        if (t > 0) tile_gemm<HID>(Hsrc, g_WhhTokP, bm, bn, acc, As, Bs);

        fuse_epilogue(acc, bm, bn, g_Xp + (size_t)t * G4, (long)TOK * G4,
                      (t > 0) ? Csrc : nullptr, Hdst, Cdst);

        grid_sync(&g_bar2, 128u * (unsigned)(t + 1));
    }
}

// ---------------- per-level parent gather (max combine) ----------------
__global__ void gather_kernel(const int* __restrict__ pidx, int l)
{
    int r   = blockIdx.x;
    int row = l * KROWS + r;
    int h   = threadIdx.x;
    __shared__ int sp[PAR];
    __shared__ int sv[PAR];
    if (h < PAR) {
        sp[h] = pidx[row*PAR + h];
        sv[h] = g_pval[row*PAR + h];
    }
    __syncthreads();
    float mh = -1e30f, mc = -1e30f;
    int has = 0;
#pragma unroll
    for (int p = 0; p < PAR; p++) {
        if (sv[p]) {
            has = 1;
            mh = fmaxf(mh, g_Hi[(size_t)sp[p]*HID + h]);
            mc = fmaxf(mc, g_Ci[(size_t)sp[p]*HID + h]);
        }
    }
    g_h0[r*HID + h] = has ? mh : 0.0f;
    g_c0[r*HID + h] = has ? mc : 0.0f;
}

// per-level fused GEMM+LSTM (8 blocks, M=128)
__global__ __launch_bounds__(256, 2) void level_kernel(int l)
{
    __shared__ float As[2*128*T_PAD];
    __shared__ float Bs[2*128*T_PAD];
    const int bn = blockIdx.x * 128;
    float acc[4][4][4];
#pragma unroll
    for (int mi = 0; mi < 4; mi++)
#pragma unroll
        for (int ni = 0; ni < 4; ni++)
#pragma unroll
            for (int r = 0; r < 4; r++) acc[mi][ni][r] = 0.0f;

    tile_gemm<HID>(g_h0, g_WhhInsP, 0, bn, acc, As, Bs);
    fuse_epilogue(acc, 0, bn, g_Gx + (size_t)l * KROWS * G4, (long)G4,
                  g_c0, g_Hi + (size_t)l * KROWS * HID, g_Ci + (size_t)l * KROWS * HID);
}

// ---------------- final: masked max over roots, then dot with Wlin ----------------
__global__ void final1_kernel()
{
    int b = blockIdx.x;
    int h = threadIdx.x;
    float m = -1e30f;
    for (int r = b*32; r < b*32 + 32; r++)
        if (g_appears[r] == 0) m = fmaxf(m, g_Hi[(size_t)r*HID + h]);
    g_partial[b*HID + h] = m;
}

__global__ void final2_kernel(const float* __restrict__ Wlin,
                              const float* __restrict__ blin,
                              float* __restrict__ out)
{
    int h = threadIdx.x;
    float m = -1e30f;
    for (int b = 0; b < 64; b++) m = fmaxf(m, g_partial[b*HID + h]);
    float v = m * Wlin[h];
    __shared__ float s[256];
    s[h] = v;
    __syncthreads();
    for (int st = 128; st > 0; st >>= 1) {
        if (h < st) s[h] += s[h + st];
        __syncthreads();
    }
    if (h == 0) out[0] = s[0] + blin[0];
}

// ---------------- launch ----------------
extern "C" void kernel_launch(void* const* d_in, const int* in_sizes, int n_in,
                              void* d_out, int out_size)
{
    const float* tokens   = (const float*)d_in[0];
    const int*   pidx     = (const int*)  d_in[1];
    const unsigned char* pval = (const unsigned char*)d_in[2];
    const float* Wih_tok  = (const float*)d_in[3];
    const float* Whh_tok  = (const float*)d_in[4];
    const float* bih_tok  = (const float*)d_in[5];
    const float* bhh_tok  = (const float*)d_in[6];
    const float* Wih_ins  = (const float*)d_in[7];
    const float* Whh_ins  = (const float*)d_in[8];
    const float* bih_ins  = (const float*)d_in[9];
    const float* bhh_ins  = (const float*)d_in[10];
    const float* Wlin     = (const float*)d_in[11];
    const float* blin     = (const float*)d_in[12];
    float* out = (float*)d_out;

    float *pXp, *pH, *pGx, *pWihTokP, *pWihInsP, *pBT, *pBI, *pWtP, *pWiP;
    cudaGetSymbolAddress((void**)&pXp,      g_Xp);
    cudaGetSymbolAddress((void**)&pH,       g_H);
    cudaGetSymbolAddress((void**)&pGx,      g_Gx);
    cudaGetSymbolAddress((void**)&pWtP,     g_WhhTokP);
    cudaGetSymbolAddress((void**)&pWiP,     g_WhhInsP);
    cudaGetSymbolAddress((void**)&pWihTokP, g_WihTokP);
    cudaGetSymbolAddress((void**)&pWihInsP, g_WihInsP);
    cudaGetSymbolAddress((void**)&pBT,      g_biasTokP);
    cudaGetSymbolAddress((void**)&pBI,      g_biasInsP);

    prep_kernel<<<1, 256>>>(pval, pidx);
    permW_kernel<<<G4, 256>>>(Whh_tok, pWtP, HID);
    permW_kernel<<<G4, 256>>>(Whh_ins, pWiP, HID);
    permW_kernel<<<G4, 256>>>(Wih_tok, pWihTokP, EMB);
    permW_kernel<<<G4, 256>>>(Wih_ins, pWihInsP, HID);
    permBias_kernel<<<4, 256>>>(bih_tok, bhh_tok, pBT);
    permBias_kernel<<<4, 256>>>(bih_ins, bhh_ins, pBI);

    // Phase 1: Xp (gate-interleaved) = tokens @ WihTokP^T + biasTokP
    mma_plain_kernel<EMB><<<dim3(8, 256), 256>>>(tokens, pWihTokP, pXp, pBT);

    // Phase 2: persistent token-LSTM recurrence (final hidden lands in g_H)
    phase2_kernel<<<128, 256>>>();

    // Phase 3a: Gx (gate-interleaved) = ins_embed @ WihInsP^T + biasInsP
    mma_plain_kernel<HID><<<dim3(8, 16), 256>>>(pH, pWihInsP, pGx, pBI);

    // Phase 3b: per-level gather (wide) + fused GEMM+LSTM
    for (int l = 0; l < LEVELS; l++) {
        gather_kernel<<<KROWS, HID>>>(pidx, l);
        level_kernel<<<8, 256>>>(l);
    }

    final1_kernel<<<64, 256>>>();
    final2_kernel<<<1, 256>>>(Wlin, blin, out);
}

// round 13
// speedup vs baseline: 1.0083x; 1.0083x over previous
#include <cuda_runtime.h>
#include <math.h>
#include <stdint.h>

#define NINS   2048
#define TOK    16
#define EMB    512
#define HID    256
#define G4     (4*HID)      // 1024
#define PAR    8
#define LEVELS 16
#define KROWS  (NINS/LEVELS) // 128
#define T_PAD  20

// ---------------- scratch (static device globals; no allocation) ----------------
__device__ float g_Xp[NINS*TOK*G4];      // gate-interleaved token input projections
__device__ float g_H[NINS*HID];
__device__ float g_C[NINS*HID];
__device__ float g_H2[NINS*HID];
__device__ float g_C2[NINS*HID];
__device__ float g_Gx[NINS*G4];          // gate-interleaved
__device__ float g_Hi[NINS*HID];
__device__ float g_Ci[NINS*HID];
__device__ float g_h0[KROWS*HID];
__device__ float g_c0[KROWS*HID];
__device__ float g_WhhTokP[G4*HID];      // gate-interleaved rows, tf32-rounded
__device__ float g_WhhInsP[G4*HID];
__device__ float g_WihTokP[G4*EMB];
__device__ float g_WihInsP[G4*HID];
__device__ float g_biasTokP[G4];
__device__ float g_biasInsP[G4];
__device__ unsigned char g_pval[NINS*PAR];
__device__ int   g_appears[NINS];
__device__ float g_partial[64*HID];
__device__ unsigned int g_bar2;

// ---------------- helpers ----------------
__device__ __forceinline__ uint32_t cvt_tf32(float v) {
    uint32_t r;
    asm("cvt.rna.tf32.f32 %0, %1;" : "=r"(r) : "f"(v));
    return r;
}
__device__ __forceinline__ void mma_tf32(float* c, uint32_t a0, uint32_t a1,
                                         uint32_t a2, uint32_t a3,
                                         uint32_t b0, uint32_t b1) {
    asm("mma.sync.aligned.m16n8k8.row.col.f32.tf32.tf32.f32 "
        "{%0,%1,%2,%3}, {%4,%5,%6,%7}, {%8,%9}, {%0,%1,%2,%3};"
        : "+f"(c[0]), "+f"(c[1]), "+f"(c[2]), "+f"(c[3])
        : "r"(a0), "r"(a1), "r"(a2), "r"(a3), "r"(b0), "r"(b1));
}
__device__ __forceinline__ void cp_async16(void* smem, const void* gmem) {
    uint32_t s = (uint32_t)__cvta_generic_to_shared(smem);
    asm volatile("cp.async.cg.shared.global [%0], [%1], 16;\n" :: "r"(s), "l"(gmem));
}

// ---------------- grid barrier (R9-proven: fence + atomicAdd poll) ----------------
__device__ __forceinline__ void grid_sync(unsigned int* bar, unsigned int target) {
    __threadfence();
    __syncthreads();
    if (threadIdx.x == 0) {
        atomicAdd(bar, 1u);
        while (atomicAdd(bar, 0u) < target) { __nanosleep(32); }
    }
    __syncthreads();
    __threadfence();
}

// ---------------- prep: pval normalize + appears + barrier reset ----------------
__global__ void prep_kernel(const unsigned char* __restrict__ pv_raw,
                            const int* __restrict__ pidx)
{
    __shared__ int s_hi, s_b0;
    __shared__ int s_app[NINS];
    int tid = threadIdx.x;
    if (tid == 0) { g_bar2 = 0u; }
    int hi = 0, b0 = 0;
    for (int i = 256 + tid; i < 4096; i += 256) {
        hi |= pv_raw[4*i+1] | pv_raw[4*i+2] | pv_raw[4*i+3];
        b0 |= pv_raw[4*i+0];
    }
    if (tid == 0) { s_hi = 0; s_b0 = 0; }
    __syncthreads();
    if (hi) atomicOr(&s_hi, 1);
    if (b0) atomicOr(&s_b0, 1);
    __syncthreads();
    int mode = (s_hi == 0) ? 0 : (s_b0 == 0 ? 1 : 2);
    for (int i = tid; i < NINS*PAR; i += 256) {
        unsigned char v;
        if (mode == 0)      v = (((const int*)pv_raw)[i]   != 0);
        else if (mode == 1) v = (((const float*)pv_raw)[i] != 0.0f);
        else                v = (pv_raw[i] != 0);
        g_pval[i] = v;
    }
    for (int i = tid; i < NINS; i += 256) s_app[i] = 0;
    __syncthreads();
    for (int i = tid; i < NINS*PAR; i += 256) {
        if (g_pval[i]) atomicAdd(&s_app[pidx[i]], 1);
    }
    __syncthreads();
    for (int i = tid; i < NINS; i += 256) g_appears[i] = s_app[i];
}

// ---------------- merged weight/bias prep ----------------
__global__ void permAll_kernel(const float* __restrict__ Whh_tok,
                               const float* __restrict__ Whh_ins,
                               const float* __restrict__ Wih_tok,
                               const float* __restrict__ Wih_ins,
                               const float* __restrict__ bih_tok,
                               const float* __restrict__ bhh_tok,
                               const float* __restrict__ bih_ins,
                               const float* __restrict__ bhh_ins)
{
    int np = blockIdx.x;
    int n  = (np & 3) * HID + (np >> 2);
    int c  = threadIdx.x;
    g_WhhTokP[(size_t)np * HID + c] = __uint_as_float(cvt_tf32(Whh_tok[(size_t)n * HID + c]));
    g_WhhInsP[(size_t)np * HID + c] = __uint_as_float(cvt_tf32(Whh_ins[(size_t)n * HID + c]));
    g_WihInsP[(size_t)np * HID + c] = __uint_as_float(cvt_tf32(Wih_ins[(size_t)n * HID + c]));
    g_WihTokP[(size_t)np * EMB + c]       = __uint_as_float(cvt_tf32(Wih_tok[(size_t)n * EMB + c]));
    g_WihTokP[(size_t)np * EMB + 256 + c] = __uint_as_float(cvt_tf32(Wih_tok[(size_t)n * EMB + 256 + c]));
    if (c == 0) {
        g_biasTokP[np] = bih_tok[n] + bhh_tok[n];
        g_biasInsP[np] = bih_ins[n] + bhh_ins[n];
    }
}

// ============================================================================
// tile GEMM (mma.sync tf32, single-pass): acc += A[bm:,:K] @ B[bn:,:K]^T
// 128x128 tile, BK=16, 2-stage cp.async, 8 warps (2x4). B pre-rounded tf32.
// ============================================================================
template<int KDIM>
__device__ __forceinline__ void tile_gemm(
    const float* __restrict__ A, const float* __restrict__ B,
    int bm, int bn, float (&acc)[4][4][4], float* As, float* Bs)
{
    const int tid  = threadIdx.x;
    const int lane = tid & 31;
    const int warp = tid >> 5;
    const int wm = (warp >> 2) * 64;
    const int wn = (warp & 3) * 32;
    const int g   = lane >> 2;
    const int tig = lane & 3;
    const int NT = KDIM / 16;

#pragma unroll
    for (int u = 0; u < 2; u++) {
        int idx = u * 256 + tid;
        int r = idx >> 2, c4 = idx & 3;
        cp_async16(As + r * T_PAD + c4 * 4, A + (size_t)(bm + r) * KDIM + c4 * 4);
        cp_async16(Bs + r * T_PAD + c4 * 4, B + (size_t)(bn + r) * KDIM + c4 * 4);
    }
    asm volatile("cp.async.commit_group;\n");

    for (int kt = 0; kt < NT; kt++) {
        int cur = kt & 1;
        if (kt + 1 < NT) {
            int nxt = (kt + 1) & 1;
            const float* Ap = A + (size_t)bm * KDIM + (kt + 1) * 16;
            const float* Bp = B + (size_t)bn * KDIM + (kt + 1) * 16;
#pragma unroll
            for (int u = 0; u < 2; u++) {
                int idx = u * 256 + tid;
                int r = idx >> 2, c4 = idx & 3;
                cp_async16(As + nxt * 128 * T_PAD + r * T_PAD + c4 * 4,
                           Ap + (size_t)r * KDIM + c4 * 4);
                cp_async16(Bs + nxt * 128 * T_PAD + r * T_PAD + c4 * 4,
                           Bp + (size_t)r * KDIM + c4 * 4);
            }
            asm volatile("cp.async.commit_group;\n");
            asm volatile("cp.async.wait_group 1;\n");
        } else {
            asm volatile("cp.async.wait_group 0;\n");
        }
        __syncthreads();

        const float* Asb = As + cur * 128 * T_PAD;
        const float* Bsb = Bs + cur * 128 * T_PAD;
#pragma unroll
        for (int ks = 0; ks < 2; ks++) {
            const int k0 = ks * 8;
            uint32_t bf[4][2];
#pragma unroll
            for (int ni = 0; ni < 4; ni++) {
                bf[ni][0] = __float_as_uint(Bsb[(wn + ni*8 + g) * T_PAD + k0 + tig]);
                bf[ni][1] = __float_as_uint(Bsb[(wn + ni*8 + g) * T_PAD + k0 + tig + 4]);
            }
            uint32_t af[4][4];
#pragma unroll
            for (int mi = 0; mi < 4; mi++) {
                int r0 = (wm + mi*16 + g) * T_PAD + k0;
                int r1 = (wm + mi*16 + 8 + g) * T_PAD + k0;
                af[mi][0] = cvt_tf32(Asb[r0 + tig]);
                af[mi][1] = cvt_tf32(Asb[r1 + tig]);
                af[mi][2] = cvt_tf32(Asb[r0 + tig + 4]);
                af[mi][3] = cvt_tf32(Asb[r1 + tig + 4]);
            }
#pragma unroll
            for (int mi = 0; mi < 4; mi++)
#pragma unroll
                for (int ni = 0; ni < 4; ni++)
                    mma_tf32(acc[mi][ni], af[mi][0], af[mi][1], af[mi][2], af[mi][3],
                             bf[ni][0], bf[ni][1]);
        }
        __syncthreads();
    }
}

// fused LSTM epilogue; Add gate-interleaved -> one float4/thread
__device__ __forceinline__ void fuse_epilogue(
    float (&acc)[4][4][4], int bm, int bn,
    const float* __restrict__ Add, long addStride,
    const float* __restrict__ Cprev,
    float* __restrict__ Hout, float* __restrict__ Cstate)
{
    const int lane = threadIdx.x & 31;
    const int warp = threadIdx.x >> 5;
    const int wm = (warp >> 2) * 64;
    const int wn = (warp & 3) * 32;
    const int g   = lane >> 2;
    const int tig = lane & 3;
#pragma unroll
    for (int mi = 0; mi < 4; mi++) {
#pragma unroll
        for (int ni = 0; ni < 4; ni++) {
            float c0 = acc[mi][ni][0], c1 = acc[mi][ni][1];
            float c2 = acc[mi][ni][2], c3 = acc[mi][ni][3];
            float x0 = __shfl_xor_sync(0xffffffffu, c0, 1);
            float x1 = __shfl_xor_sync(0xffffffffu, c1, 1);
            float x2 = __shfl_xor_sync(0xffffffffu, c2, 1);
            float x3 = __shfl_xor_sync(0xffffffffu, c3, 1);
            int q = tig >> 1;
            int h = (bn + wn + ni*8 + q*4) >> 2;
            int row;
            float gi, gf, gg, go;
            if ((tig & 1) == 0) {
                row = bm + wm + mi*16 + g;
                gi = c0; gf = c1; gg = x0; go = x1;
            } else {
                row = bm + wm + mi*16 + 8 + g;
                gi = x2; gf = x3; gg = c2; go = c3;
            }
            const float4 ad4 = *(const float4*)(Add + (size_t)row * addStride + 4*h);
            gi += ad4.x;
            gf += ad4.y;
            gg += ad4.z;
            go += ad4.w;
            float c = Cprev ? Cprev[(size_t)row * HID + h] : 0.0f;
            float si = 1.0f / (1.0f + expf(-gi));
            float sf = 1.0f / (1.0f + expf(-gf));
            float so = 1.0f / (1.0f + expf(-go));
            float cn = sf * c + si * tanhf(gg);
            float hn = so * tanhf(cn);
            Cstate[(size_t)row * HID + h] = cn;
            Hout[(size_t)row * HID + h]   = hn;
        }
    }
}

// ============================================================================
// Plain GEMM kernel (phase-1 Xp and phase-3a Gx): C = A@B^T + bias (permuted)
// ============================================================================
template<int KDIM>
__global__ __launch_bounds__(256, 2) void mma_plain_kernel(
    const float* __restrict__ A, const float* __restrict__ B,
    float* __restrict__ Cout, const float* __restrict__ bias)
{
    __shared__ float As[2*128*T_PAD];
    __shared__ float Bs[2*128*T_PAD];
    const int bm = blockIdx.y * 128;
    const int bn = blockIdx.x * 128;
    const int lane = threadIdx.x & 31;
    const int warp = threadIdx.x >> 5;
    const int wm = (warp >> 2) * 64;
    const int wn = (warp & 3) * 32;
    const int g   = lane >> 2;
    const int tig = lane & 3;

    float acc[4][4][4];
#pragma unroll
    for (int mi = 0; mi < 4; mi++)
#pragma unroll
        for (int ni = 0; ni < 4; ni++)
#pragma unroll
            for (int r = 0; r < 4; r++) acc[mi][ni][r] = 0.0f;

    tile_gemm<KDIM>(A, B, bm, bn, acc, As, Bs);

#pragma unroll
    for (int mi = 0; mi < 4; mi++) {
        int r0 = bm + wm + mi*16 + g;
        int r1 = r0 + 8;
#pragma unroll
        for (int ni = 0; ni < 4; ni++) {
            int c = bn + wn + ni*8 + tig*2;
            float bb0 = bias[c];
            float bb1 = bias[c+1];
            float2 v0 = make_float2(acc[mi][ni][0] + bb0, acc[mi][ni][1] + bb1);
            float2 v1 = make_float2(acc[mi][ni][2] + bb0, acc[mi][ni][3] + bb1);
            *(float2*)(Cout + (size_t)r0 * G4 + c) = v0;
            *(float2*)(Cout + (size_t)r1 * G4 + c) = v1;
        }
    }
}

// ============================================================================
// Phase-2 persistent kernel: all 16 token-LSTM steps. 128 blocks.
// ============================================================================
__global__ __launch_bounds__(256, 2) void phase2_kernel()
{
    __shared__ float As[2*128*T_PAD];
    __shared__ float Bs[2*128*T_PAD];
    const int bm = (blockIdx.x >> 3) * 128;
    const int bn = (blockIdx.x & 7) * 128;

    for (int t = 0; t < TOK; t++) {
        float acc[4][4][4];
#pragma unroll
        for (int mi = 0; mi < 4; mi++)
#pragma unroll
            for (int ni = 0; ni < 4; ni++)
#pragma unroll
                for (int r = 0; r < 4; r++) acc[mi][ni][r] = 0.0f;

        const float* Hsrc = (t & 1) ? g_H2 : g_H;
        const float* Csrc = (t & 1) ? g_C2 : g_C;
        float* Hdst = (t & 1) ? g_H : g_H2;
        float* Cdst = (t & 1) ? g_C : g_C2;

        if (t > 0) tile_gemm<HID>(Hsrc, g_WhhTokP, bm, bn, acc, As, Bs);

        fuse_epilogue(acc, bm, bn, g_Xp + (size_t)t * G4, (long)TOK * G4,
                      (t > 0) ? Csrc : nullptr, Hdst, Cdst);

        grid_sync(&g_bar2, 128u * (unsigned)(t + 1));
    }
}

// ---------------- per-level parent gather (max combine) ----------------
__global__ void gather_kernel(const int* __restrict__ pidx, int l)
{
    int r   = blockIdx.x;
    int row = l * KROWS + r;
    int h   = threadIdx.x;
    __shared__ int sp[PAR];
    __shared__ int sv[PAR];
    if (h < PAR) {
        sp[h] = pidx[row*PAR + h];
        sv[h] = g_pval[row*PAR + h];
    }
    __syncthreads();
    float mh = -1e30f, mc = -1e30f;
    int has = 0;
#pragma unroll
    for (int p = 0; p < PAR; p++) {
        if (sv[p]) {
            has = 1;
            mh = fmaxf(mh, g_Hi[(size_t)sp[p]*HID + h]);
            mc = fmaxf(mc, g_Ci[(size_t)sp[p]*HID + h]);
        }
    }
    g_h0[r*HID + h] = has ? mh : 0.0f;
    g_c0[r*HID + h] = has ? mc : 0.0f;
}

// per-level fused GEMM+LSTM (8 blocks, M=128)
__global__ __launch_bounds__(256, 2) void level_kernel(int l)
{
    __shared__ float As[2*128*T_PAD];
    __shared__ float Bs[2*128*T_PAD];
    const int bn = blockIdx.x * 128;
    float acc[4][4][4];
#pragma unroll
    for (int mi = 0; mi < 4; mi++)
#pragma unroll
        for (int ni = 0; ni < 4; ni++)
#pragma unroll
            for (int r = 0; r < 4; r++) acc[mi][ni][r] = 0.0f;

    tile_gemm<HID>(g_h0, g_WhhInsP, 0, bn, acc, As, Bs);
    fuse_epilogue(acc, 0, bn, g_Gx + (size_t)l * KROWS * G4, (long)G4,
                  g_c0, g_Hi + (size_t)l * KROWS * HID, g_Ci + (size_t)l * KROWS * HID);
}

// ---------------- final: masked max over roots, then dot with Wlin ----------------
__global__ void final1_kernel()
{
    int b = blockIdx.x;
    int h = threadIdx.x;
    float m = -1e30f;
    for (int r = b*32; r < b*32 + 32; r++)
        if (g_appears[r] == 0) m = fmaxf(m, g_Hi[(size_t)r*HID + h]);
    g_partial[b*HID + h] = m;
}

__global__ void final2_kernel(const float* __restrict__ Wlin,
                              const float* __restrict__ blin,
                              float* __restrict__ out)
{
    int h = threadIdx.x;
    float m = -1e30f;
    for (int b = 0; b < 64; b++) m = fmaxf(m, g_partial[b*HID + h]);
    float v = m * Wlin[h];
    __shared__ float s[256];
    s[h] = v;
    __syncthreads();
    for (int st = 128; st > 0; st >>= 1) {
        if (h < st) s[h] += s[h + st];
        __syncthreads();
    }
    if (h == 0) out[0] = s[0] + blin[0];
}

// ---------------- launch ----------------
extern "C" void kernel_launch(void* const* d_in, const int* in_sizes, int n_in,
                              void* d_out, int out_size)
{
    const float* tokens   = (const float*)d_in[0];
    const int*   pidx     = (const int*)  d_in[1];
    const unsigned char* pval = (const unsigned char*)d_in[2];
    const float* Wih_tok  = (const float*)d_in[3];
    const float* Whh_tok  = (const float*)d_in[4];
    const float* bih_tok  = (const float*)d_in[5];
    const float* bhh_tok  = (const float*)d_in[6];
    const float* Wih_ins  = (const float*)d_in[7];
    const float* Whh_ins  = (const float*)d_in[8];
    const float* bih_ins  = (const float*)d_in[9];
    const float* bhh_ins  = (const float*)d_in[10];
    const float* Wlin     = (const float*)d_in[11];
    const float* blin     = (const float*)d_in[12];
    float* out = (float*)d_out;

    float *pXp, *pH, *pGx, *pWihTokP, *pWihInsP, *pBT, *pBI;
    cudaGetSymbolAddress((void**)&pXp,      g_Xp);
    cudaGetSymbolAddress((void**)&pH,       g_H);
    cudaGetSymbolAddress((void**)&pGx,      g_Gx);
    cudaGetSymbolAddress((void**)&pWihTokP, g_WihTokP);
    cudaGetSymbolAddress((void**)&pWihInsP, g_WihInsP);
    cudaGetSymbolAddress((void**)&pBT,      g_biasTokP);
    cudaGetSymbolAddress((void**)&pBI,      g_biasInsP);

    prep_kernel<<<1, 256>>>(pval, pidx);
    permAll_kernel<<<G4, 256>>>(Whh_tok, Whh_ins, Wih_tok, Wih_ins,
                                bih_tok, bhh_tok, bih_ins, bhh_ins);

    // Phase 1: Xp (gate-interleaved) = tokens @ WihTokP^T + biasTokP
    mma_plain_kernel<EMB><<<dim3(8, 256), 256>>>(tokens, pWihTokP, pXp, pBT);

    // Phase 2: persistent token-LSTM recurrence (final hidden lands in g_H)
    phase2_kernel<<<128, 256>>>();

    // Phase 3a: Gx (gate-interleaved) = ins_embed @ WihInsP^T + biasInsP
    mma_plain_kernel<HID><<<dim3(8, 16), 256>>>(pH, pWihInsP, pGx, pBI);

    // Phase 3b: per-level gather (wide) + fused GEMM+LSTM
    for (int l = 0; l < LEVELS; l++) {
        gather_kernel<<<KROWS, HID>>>(pidx, l);
        level_kernel<<<8, 256>>>(l);
    }

    final1_kernel<<<64, 256>>>();
    final2_kernel<<<1, 256>>>(Wlin, blin, out);
}

// round 14
// speedup vs baseline: 1.0639x; 1.0551x over previous
#include <cuda_runtime.h>
#include <math.h>
#include <stdint.h>

#define NINS   2048
#define TOK    16
#define EMB    512
#define HID    256
#define G4     (4*HID)      // 1024
#define PAR    8
#define LEVELS 16
#define KROWS  (NINS/LEVELS) // 128
#define T_PAD  20
#define P2_SMEM ((16*128*20 + 2*128*20) * 4)   // 184320 bytes

// ---------------- scratch (static device globals; no allocation) ----------------
__device__ float g_Xp[NINS*TOK*G4];      // gate-interleaved token input projections
__device__ float g_H[NINS*HID];
__device__ float g_H2[NINS*HID];
__device__ float g_Gx[NINS*G4];          // gate-interleaved
__device__ float g_Hi[NINS*HID];
__device__ float g_Ci[NINS*HID];
__device__ float g_h0[KROWS*HID];
__device__ float g_c0[KROWS*HID];
__device__ float g_WhhTokP[G4*HID];      // gate-interleaved rows, tf32-rounded
__device__ float g_WhhInsP[G4*HID];
__device__ float g_WihTokP[G4*EMB];
__device__ float g_WihInsP[G4*HID];
__device__ float g_biasTokP[G4];
__device__ float g_biasInsP[G4];
__device__ unsigned char g_pval[NINS*PAR];
__device__ int   g_appears[NINS];
__device__ float g_partial[64*HID];
__device__ unsigned int g_bar2;

// ---------------- helpers ----------------
__device__ __forceinline__ uint32_t cvt_tf32(float v) {
    uint32_t r;
    asm("cvt.rna.tf32.f32 %0, %1;" : "=r"(r) : "f"(v));
    return r;
}
__device__ __forceinline__ void mma_tf32(float* c, uint32_t a0, uint32_t a1,
                                         uint32_t a2, uint32_t a3,
                                         uint32_t b0, uint32_t b1) {
    asm("mma.sync.aligned.m16n8k8.row.col.f32.tf32.tf32.f32 "
        "{%0,%1,%2,%3}, {%4,%5,%6,%7}, {%8,%9}, {%0,%1,%2,%3};"
        : "+f"(c[0]), "+f"(c[1]), "+f"(c[2]), "+f"(c[3])
        : "r"(a0), "r"(a1), "r"(a2), "r"(a3), "r"(b0), "r"(b1));
}
__device__ __forceinline__ void cp_async16(void* smem, const void* gmem) {
    uint32_t s = (uint32_t)__cvta_generic_to_shared(smem);
    asm volatile("cp.async.cg.shared.global [%0], [%1], 16;\n" :: "r"(s), "l"(gmem));
}

// ---------------- grid barrier (R9/R13-proven: fence + atomicAdd poll) ----------------
__device__ __forceinline__ void grid_sync(unsigned int* bar, unsigned int target) {
    __threadfence();
    __syncthreads();
    if (threadIdx.x == 0) {
        atomicAdd(bar, 1u);
        while (atomicAdd(bar, 0u) < target) { __nanosleep(32); }
    }
    __syncthreads();
    __threadfence();
}

// ---------------- prep: pval normalize + appears + barrier reset ----------------
__global__ void prep_kernel(const unsigned char* __restrict__ pv_raw,
                            const int* __restrict__ pidx)
{
    __shared__ int s_hi, s_b0;
    __shared__ int s_app[NINS];
    int tid = threadIdx.x;
    if (tid == 0) { g_bar2 = 0u; }
    int hi = 0, b0 = 0;
    for (int i = 256 + tid; i < 4096; i += 256) {
        hi |= pv_raw[4*i+1] | pv_raw[4*i+2] | pv_raw[4*i+3];
        b0 |= pv_raw[4*i+0];
    }
    if (tid == 0) { s_hi = 0; s_b0 = 0; }
    __syncthreads();
    if (hi) atomicOr(&s_hi, 1);
    if (b0) atomicOr(&s_b0, 1);
    __syncthreads();
    int mode = (s_hi == 0) ? 0 : (s_b0 == 0 ? 1 : 2);
    for (int i = tid; i < NINS*PAR; i += 256) {
        unsigned char v;
        if (mode == 0)      v = (((const int*)pv_raw)[i]   != 0);
        else if (mode == 1) v = (((const float*)pv_raw)[i] != 0.0f);
        else                v = (pv_raw[i] != 0);
        g_pval[i] = v;
    }
    for (int i = tid; i < NINS; i += 256) s_app[i] = 0;
    __syncthreads();
    for (int i = tid; i < NINS*PAR; i += 256) {
        if (g_pval[i]) atomicAdd(&s_app[pidx[i]], 1);
    }
    __syncthreads();
    for (int i = tid; i < NINS; i += 256) g_appears[i] = s_app[i];
}

// ---------------- merged weight/bias prep ----------------
__global__ void permAll_kernel(const float* __restrict__ Whh_tok,
                               const float* __restrict__ Whh_ins,
                               const float* __restrict__ Wih_tok,
                               const float* __restrict__ Wih_ins,
                               const float* __restrict__ bih_tok,
                               const float* __restrict__ bhh_tok,
                               const float* __restrict__ bih_ins,
                               const float* __restrict__ bhh_ins)
{
    int np = blockIdx.x;
    int n  = (np & 3) * HID + (np >> 2);
    int c  = threadIdx.x;
    g_WhhTokP[(size_t)np * HID + c] = __uint_as_float(cvt_tf32(Whh_tok[(size_t)n * HID + c]));
    g_WhhInsP[(size_t)np * HID + c] = __uint_as_float(cvt_tf32(Whh_ins[(size_t)n * HID + c]));
    g_WihInsP[(size_t)np * HID + c] = __uint_as_float(cvt_tf32(Wih_ins[(size_t)n * HID + c]));
    g_WihTokP[(size_t)np * EMB + c]       = __uint_as_float(cvt_tf32(Wih_tok[(size_t)n * EMB + c]));
    g_WihTokP[(size_t)np * EMB + 256 + c] = __uint_as_float(cvt_tf32(Wih_tok[(size_t)n * EMB + 256 + c]));
    if (c == 0) {
        g_biasTokP[np] = bih_tok[n] + bhh_tok[n];
        g_biasInsP[np] = bih_ins[n] + bhh_ins[n];
    }
}

// ============================================================================
// tile GEMM (mma.sync tf32, single-pass): acc += A[bm:,:K] @ B[bn:,:K]^T
// 128x128 tile, BK=16, 2-stage cp.async, 8 warps (2x4). B pre-rounded tf32.
// ============================================================================
template<int KDIM>
__device__ __forceinline__ void tile_gemm(
    const float* __restrict__ A, const float* __restrict__ B,
    int bm, int bn, float (&acc)[4][4][4], float* As, float* Bs)
{
    const int tid  = threadIdx.x;
    const int lane = tid & 31;
    const int warp = tid >> 5;
    const int wm = (warp >> 2) * 64;
    const int wn = (warp & 3) * 32;
    const int g   = lane >> 2;
    const int tig = lane & 3;
    const int NT = KDIM / 16;

#pragma unroll
    for (int u = 0; u < 2; u++) {
        int idx = u * 256 + tid;
        int r = idx >> 2, c4 = idx & 3;
        cp_async16(As + r * T_PAD + c4 * 4, A + (size_t)(bm + r) * KDIM + c4 * 4);
        cp_async16(Bs + r * T_PAD + c4 * 4, B + (size_t)(bn + r) * KDIM + c4 * 4);
    }
    asm volatile("cp.async.commit_group;\n");

    for (int kt = 0; kt < NT; kt++) {
        int cur = kt & 1;
        if (kt + 1 < NT) {
            int nxt = (kt + 1) & 1;
            const float* Ap = A + (size_t)bm * KDIM + (kt + 1) * 16;
            const float* Bp = B + (size_t)bn * KDIM + (kt + 1) * 16;
#pragma unroll
            for (int u = 0; u < 2; u++) {
                int idx = u * 256 + tid;
                int r = idx >> 2, c4 = idx & 3;
                cp_async16(As + nxt * 128 * T_PAD + r * T_PAD + c4 * 4,
                           Ap + (size_t)r * KDIM + c4 * 4);
                cp_async16(Bs + nxt * 128 * T_PAD + r * T_PAD + c4 * 4,
                           Bp + (size_t)r * KDIM + c4 * 4);
            }
            asm volatile("cp.async.commit_group;\n");
            asm volatile("cp.async.wait_group 1;\n");
        } else {
            asm volatile("cp.async.wait_group 0;\n");
        }
        __syncthreads();

        const float* Asb = As + cur * 128 * T_PAD;
        const float* Bsb = Bs + cur * 128 * T_PAD;
#pragma unroll
        for (int ks = 0; ks < 2; ks++) {
            const int k0 = ks * 8;
            uint32_t bf[4][2];
#pragma unroll
            for (int ni = 0; ni < 4; ni++) {
                bf[ni][0] = __float_as_uint(Bsb[(wn + ni*8 + g) * T_PAD + k0 + tig]);
                bf[ni][1] = __float_as_uint(Bsb[(wn + ni*8 + g) * T_PAD + k0 + tig + 4]);
            }
            uint32_t af[4][4];
#pragma unroll
            for (int mi = 0; mi < 4; mi++) {
                int r0 = (wm + mi*16 + g) * T_PAD + k0;
                int r1 = (wm + mi*16 + 8 + g) * T_PAD + k0;
                af[mi][0] = cvt_tf32(Asb[r0 + tig]);
                af[mi][1] = cvt_tf32(Asb[r1 + tig]);
                af[mi][2] = cvt_tf32(Asb[r0 + tig + 4]);
                af[mi][3] = cvt_tf32(Asb[r1 + tig + 4]);
            }
#pragma unroll
            for (int mi = 0; mi < 4; mi++)
#pragma unroll
                for (int ni = 0; ni < 4; ni++)
                    mma_tf32(acc[mi][ni], af[mi][0], af[mi][1], af[mi][2], af[mi][3],
                             bf[ni][0], bf[ni][1]);
        }
        __syncthreads();
    }
}

// fused LSTM epilogue (global C); Add gate-interleaved -> one float4/thread
__device__ __forceinline__ void fuse_epilogue(
    float (&acc)[4][4][4], int bm, int bn,
    const float* __restrict__ Add, long addStride,
    const float* __restrict__ Cprev,
    float* __restrict__ Hout, float* __restrict__ Cstate)
{
    const int lane = threadIdx.x & 31;
    const int warp = threadIdx.x >> 5;
    const int wm = (warp >> 2) * 64;
    const int wn = (warp & 3) * 32;
    const int g   = lane >> 2;
    const int tig = lane & 3;
#pragma unroll
    for (int mi = 0; mi < 4; mi++) {
#pragma unroll
        for (int ni = 0; ni < 4; ni++) {
            float c0 = acc[mi][ni][0], c1 = acc[mi][ni][1];
            float c2 = acc[mi][ni][2], c3 = acc[mi][ni][3];
            float x0 = __shfl_xor_sync(0xffffffffu, c0, 1);
            float x1 = __shfl_xor_sync(0xffffffffu, c1, 1);
            float x2 = __shfl_xor_sync(0xffffffffu, c2, 1);
            float x3 = __shfl_xor_sync(0xffffffffu, c3, 1);
            int q = tig >> 1;
            int h = (bn + wn + ni*8 + q*4) >> 2;
            int row;
            float gi, gf, gg, go;
            if ((tig & 1) == 0) {
                row = bm + wm + mi*16 + g;
                gi = c0; gf = c1; gg = x0; go = x1;
            } else {
                row = bm + wm + mi*16 + 8 + g;
                gi = x2; gf = x3; gg = c2; go = c3;
            }
            const float4 ad4 = *(const float4*)(Add + (size_t)row * addStride + 4*h);
            gi += ad4.x;
            gf += ad4.y;
            gg += ad4.z;
            go += ad4.w;
            float c = Cprev ? Cprev[(size_t)row * HID + h] : 0.0f;
            float si = 1.0f / (1.0f + expf(-gi));
            float sf = 1.0f / (1.0f + expf(-gf));
            float so = 1.0f / (1.0f + expf(-go));
            float cn = sf * c + si * tanhf(gg);
            float hn = so * tanhf(cn);
            Cstate[(size_t)row * HID + h] = cn;
            Hout[(size_t)row * HID + h]   = hn;
        }
    }
}

// ============================================================================
// Plain GEMM kernel (phase-1 Xp and phase-3a Gx): C = A@B^T + bias (permuted)
// ============================================================================
template<int KDIM>
__global__ __launch_bounds__(256, 2) void mma_plain_kernel(
    const float* __restrict__ A, const float* __restrict__ B,
    float* __restrict__ Cout, const float* __restrict__ bias)
{
    __shared__ float As[2*128*T_PAD];
    __shared__ float Bs[2*128*T_PAD];
    const int bm = blockIdx.y * 128;
    const int bn = blockIdx.x * 128;
    const int lane = threadIdx.x & 31;
    const int warp = threadIdx.x >> 5;
    const int wm = (warp >> 2) * 64;
    const int wn = (warp & 3) * 32;
    const int g   = lane >> 2;
    const int tig = lane & 3;

    float acc[4][4][4];
#pragma unroll
    for (int mi = 0; mi < 4; mi++)
#pragma unroll
        for (int ni = 0; ni < 4; ni++)
#pragma unroll
            for (int r = 0; r < 4; r++) acc[mi][ni][r] = 0.0f;

    tile_gemm<KDIM>(A, B, bm, bn, acc, As, Bs);

#pragma unroll
    for (int mi = 0; mi < 4; mi++) {
        int r0 = bm + wm + mi*16 + g;
        int r1 = r0 + 8;
#pragma unroll
        for (int ni = 0; ni < 4; ni++) {
            int c = bn + wn + ni*8 + tig*2;
            float bb0 = bias[c];
            float bb1 = bias[c+1];
            float2 v0 = make_float2(acc[mi][ni][0] + bb0, acc[mi][ni][1] + bb1);
            float2 v1 = make_float2(acc[mi][ni][2] + bb0, acc[mi][ni][3] + bb1);
            *(float2*)(Cout + (size_t)r0 * G4 + c) = v0;
            *(float2*)(Cout + (size_t)r1 * G4 + c) = v1;
        }
    }
}

// ============================================================================
// Phase-2 persistent kernel: all 16 token-LSTM steps. 128 blocks.
// B tile resident in smem for all steps; C state resident in registers.
// ============================================================================
__global__ __launch_bounds__(256) void phase2_kernel()
{
    extern __shared__ float sm[];
    float* Bres = sm;                    // 16 chunks x [128 x 16], row stride 20
    float* As   = sm + 16*128*T_PAD;     // 2-stage A buffer

    const int tid  = threadIdx.x;
    const int lane = tid & 31;
    const int warp = tid >> 5;
    const int wm = (warp >> 2) * 64;
    const int wn = (warp & 3) * 32;
    const int g   = lane >> 2;
    const int tig = lane & 3;
    const int bm = (blockIdx.x >> 3) * 128;
    const int bn = (blockIdx.x & 7) * 128;

    // Load resident B once (all 16 K-chunks)
#pragma unroll
    for (int kt = 0; kt < 16; kt++) {
#pragma unroll
        for (int u = 0; u < 2; u++) {
            int idx = u * 256 + tid;
            int r = idx >> 2, c4 = idx & 3;
            cp_async16(Bres + kt*128*T_PAD + r*T_PAD + c4*4,
                       g_WhhTokP + (size_t)(bn + r) * HID + kt*16 + c4*4);
        }
    }
    asm volatile("cp.async.commit_group;\n");
    asm volatile("cp.async.wait_group 0;\n");
    __syncthreads();

    // register-resident C state: one (row,h) cell per (mi,ni)
    float cst[4][4];
#pragma unroll
    for (int mi = 0; mi < 4; mi++)
#pragma unroll
        for (int ni = 0; ni < 4; ni++) cst[mi][ni] = 0.0f;

    for (int t = 0; t < TOK; t++) {
        float acc[4][4][4];
#pragma unroll
        for (int mi = 0; mi < 4; mi++)
#pragma unroll
            for (int ni = 0; ni < 4; ni++)
#pragma unroll
                for (int r = 0; r < 4; r++) acc[mi][ni][r] = 0.0f;

        const float* Aglob = (t & 1) ? g_H2 : g_H;
        float* Hdst = (t & 1) ? g_H : g_H2;

        if (t > 0) {
            // prefetch A chunk 0
#pragma unroll
            for (int u = 0; u < 2; u++) {
                int idx = u * 256 + tid;
                int r = idx >> 2, c4 = idx & 3;
                cp_async16(As + r*T_PAD + c4*4, Aglob + (size_t)(bm + r) * HID + c4*4);
            }
            asm volatile("cp.async.commit_group;\n");

            for (int kt = 0; kt < 16; kt++) {
                int cur = kt & 1;
                if (kt + 1 < 16) {
                    int nxt = (kt + 1) & 1;
#pragma unroll
                    for (int u = 0; u < 2; u++) {
                        int idx = u * 256 + tid;
                        int r = idx >> 2, c4 = idx & 3;
                        cp_async16(As + nxt*128*T_PAD + r*T_PAD + c4*4,
                                   Aglob + (size_t)(bm + r) * HID + (kt+1)*16 + c4*4);
                    }
                    asm volatile("cp.async.commit_group;\n");
                    asm volatile("cp.async.wait_group 1;\n");
                } else {
                    asm volatile("cp.async.wait_group 0;\n");
                }
                __syncthreads();

                const float* Asb = As + cur*128*T_PAD;
                const float* Bsb = Bres + kt*128*T_PAD;
#pragma unroll
                for (int ks = 0; ks < 2; ks++) {
                    const int k0 = ks * 8;
                    uint32_t bf[4][2];
#pragma unroll
                    for (int ni = 0; ni < 4; ni++) {
                        bf[ni][0] = __float_as_uint(Bsb[(wn + ni*8 + g) * T_PAD + k0 + tig]);
                        bf[ni][1] = __float_as_uint(Bsb[(wn + ni*8 + g) * T_PAD + k0 + tig + 4]);
                    }
                    uint32_t af[4][4];
#pragma unroll
                    for (int mi = 0; mi < 4; mi++) {
                        int r0 = (wm + mi*16 + g) * T_PAD + k0;
                        int r1 = (wm + mi*16 + 8 + g) * T_PAD + k0;
                        af[mi][0] = cvt_tf32(Asb[r0 + tig]);
                        af[mi][1] = cvt_tf32(Asb[r1 + tig]);
                        af[mi][2] = cvt_tf32(Asb[r0 + tig + 4]);
                        af[mi][3] = cvt_tf32(Asb[r1 + tig + 4]);
                    }
#pragma unroll
                    for (int mi = 0; mi < 4; mi++)
#pragma unroll
                        for (int ni = 0; ni < 4; ni++)
                            mma_tf32(acc[mi][ni], af[mi][0], af[mi][1], af[mi][2], af[mi][3],
                                     bf[ni][0], bf[ni][1]);
                }
                __syncthreads();
            }
        }

        // epilogue: register C, gate-interleaved Xp float4, write H only
#pragma unroll
        for (int mi = 0; mi < 4; mi++) {
#pragma unroll
            for (int ni = 0; ni < 4; ni++) {
                float c0 = acc[mi][ni][0], c1 = acc[mi][ni][1];
                float c2 = acc[mi][ni][2], c3 = acc[mi][ni][3];
                float x0 = __shfl_xor_sync(0xffffffffu, c0, 1);
                float x1 = __shfl_xor_sync(0xffffffffu, c1, 1);
                float x2 = __shfl_xor_sync(0xffffffffu, c2, 1);
                float x3 = __shfl_xor_sync(0xffffffffu, c3, 1);
                int q = tig >> 1;
                int h = (bn + wn + ni*8 + q*4) >> 2;
                int row;
                float gi, gf, gg, go;
                if ((tig & 1) == 0) {
                    row = bm + wm + mi*16 + g;
                    gi = c0; gf = c1; gg = x0; go = x1;
                } else {
                    row = bm + wm + mi*16 + 8 + g;
                    gi = x2; gf = x3; gg = c2; go = c3;
                }
                const float4 ad4 = *(const float4*)(g_Xp + ((size_t)row * TOK + t) * G4 + 4*h);
                gi += ad4.x;
                gf += ad4.y;
                gg += ad4.z;
                go += ad4.w;
                float c = cst[mi][ni];
                float si = 1.0f / (1.0f + expf(-gi));
                float sf = 1.0f / (1.0f + expf(-gf));
                float so = 1.0f / (1.0f + expf(-go));
                float cn = sf * c + si * tanhf(gg);
                float hn = so * tanhf(cn);
                cst[mi][ni] = cn;
                Hdst[(size_t)row * HID + h] = hn;
            }
        }

        if (t + 1 < TOK)
            grid_sync(&g_bar2, 128u * (unsigned)(t + 1));
    }
}

// ---------------- per-level parent gather (max combine) ----------------
__global__ void gather_kernel(const int* __restrict__ pidx, int l)
{
    int r   = blockIdx.x;
    int row = l * KROWS + r;
    int h   = threadIdx.x;
    __shared__ int sp[PAR];
    __shared__ int sv[PAR];
    if (h < PAR) {
        sp[h] = pidx[row*PAR + h];
        sv[h] = g_pval[row*PAR + h];
    }
    __syncthreads();
    float mh = -1e30f, mc = -1e30f;
    int has = 0;
#pragma unroll
    for (int p = 0; p < PAR; p++) {
        if (sv[p]) {
            has = 1;
            mh = fmaxf(mh, g_Hi[(size_t)sp[p]*HID + h]);
            mc = fmaxf(mc, g_Ci[(size_t)sp[p]*HID + h]);
        }
    }
    g_h0[r*HID + h] = has ? mh : 0.0f;
    g_c0[r*HID + h] = has ? mc : 0.0f;
}

// per-level fused GEMM+LSTM (8 blocks, M=128)
__global__ __launch_bounds__(256, 2) void level_kernel(int l)
{
    __shared__ float As[2*128*T_PAD];
    __shared__ float Bs[2*128*T_PAD];
    const int bn = blockIdx.x * 128;
    float acc[4][4][4];
#pragma unroll
    for (int mi = 0; mi < 4; mi++)
#pragma unroll
        for (int ni = 0; ni < 4; ni++)
#pragma unroll
            for (int r = 0; r < 4; r++) acc[mi][ni][r] = 0.0f;

    tile_gemm<HID>(g_h0, g_WhhInsP, 0, bn, acc, As, Bs);
    fuse_epilogue(acc, 0, bn, g_Gx + (size_t)l * KROWS * G4, (long)G4,
                  g_c0, g_Hi + (size_t)l * KROWS * HID, g_Ci + (size_t)l * KROWS * HID);
}

// ---------------- final: masked max over roots, then dot with Wlin ----------------
__global__ void final1_kernel()
{
    int b = blockIdx.x;
    int h = threadIdx.x;
    float m = -1e30f;
    for (int r = b*32; r < b*32 + 32; r++)
        if (g_appears[r] == 0) m = fmaxf(m, g_Hi[(size_t)r*HID + h]);
    g_partial[b*HID + h] = m;
}

__global__ void final2_kernel(const float* __restrict__ Wlin,
                              const float* __restrict__ blin,
                              float* __restrict__ out)
{
    int h = threadIdx.x;
    float m = -1e30f;
    for (int b = 0; b < 64; b++) m = fmaxf(m, g_partial[b*HID + h]);
    float v = m * Wlin[h];
    __shared__ float s[256];
    s[h] = v;
    __syncthreads();
    for (int st = 128; st > 0; st >>= 1) {
        if (h < st) s[h] += s[h + st];
        __syncthreads();
    }
    if (h == 0) out[0] = s[0] + blin[0];
}

// ---------------- launch ----------------
extern "C" void kernel_launch(void* const* d_in, const int* in_sizes, int n_in,
                              void* d_out, int out_size)
{
    const float* tokens   = (const float*)d_in[0];
    const int*   pidx     = (const int*)  d_in[1];
    const unsigned char* pval = (const unsigned char*)d_in[2];
    const float* Wih_tok  = (const float*)d_in[3];
    const float* Whh_tok  = (const float*)d_in[4];
    const float* bih_tok  = (const float*)d_in[5];
    const float* bhh_tok  = (const float*)d_in[6];
    const float* Wih_ins  = (const float*)d_in[7];
    const float* Whh_ins  = (const float*)d_in[8];
    const float* bih_ins  = (const float*)d_in[9];
    const float* bhh_ins  = (const float*)d_in[10];
    const float* Wlin     = (const float*)d_in[11];
    const float* blin     = (const float*)d_in[12];
    float* out = (float*)d_out;

    float *pXp, *pH, *pGx, *pWihTokP, *pWihInsP, *pBT, *pBI;
    cudaGetSymbolAddress((void**)&pXp,      g_Xp);
    cudaGetSymbolAddress((void**)&pH,       g_H);
    cudaGetSymbolAddress((void**)&pGx,      g_Gx);
    cudaGetSymbolAddress((void**)&pWihTokP, g_WihTokP);
    cudaGetSymbolAddress((void**)&pWihInsP, g_WihInsP);
    cudaGetSymbolAddress((void**)&pBT,      g_biasTokP);
    cudaGetSymbolAddress((void**)&pBI,      g_biasInsP);

    cudaFuncSetAttribute(phase2_kernel, cudaFuncAttributeMaxDynamicSharedMemorySize, P2_SMEM);

    prep_kernel<<<1, 256>>>(pval, pidx);
    permAll_kernel<<<G4, 256>>>(Whh_tok, Whh_ins, Wih_tok, Wih_ins,
                                bih_tok, bhh_tok, bih_ins, bhh_ins);

    // Phase 1: Xp (gate-interleaved) = tokens @ WihTokP^T + biasTokP
    mma_plain_kernel<EMB><<<dim3(8, 256), 256>>>(tokens, pWihTokP, pXp, pBT);

    // Phase 2: persistent token-LSTM recurrence (final hidden lands in g_H)
    phase2_kernel<<<128, 256, P2_SMEM>>>();

    // Phase 3a: Gx (gate-interleaved) = ins_embed @ WihInsP^T + biasInsP
    mma_plain_kernel<HID><<<dim3(8, 16), 256>>>(pH, pWihInsP, pGx, pBI);

    // Phase 3b: per-level gather (wide) + fused GEMM+LSTM
    for (int l = 0; l < LEVELS; l++) {
        gather_kernel<<<KROWS, HID>>>(pidx, l);
        level_kernel<<<8, 256>>>(l);
    }

    final1_kernel<<<64, 256>>>();
    final2_kernel<<<1, 256>>>(Wlin, blin, out);
}

// round 15
// speedup vs baseline: 1.1750x; 1.1044x over previous
#include <cuda_runtime.h>
#include <cuda_bf16.h>
#include <math.h>
#include <stdint.h>

#define NINS   2048
#define TOK    16
#define EMB    512
#define HID    256
#define G4     (4*HID)      // 1024
#define PAR    8
#define LEVELS 16
#define KROWS  (NINS/LEVELS) // 128
#define T_PAD  20
// phase2 dynamic smem: A fp32 [128 x 260] + B bf16 [128 x 264]
#define P2_SMEM (128*260*4 + 128*264*2)          // 200704
// phase1 dynamic smem: A fp32 2 x [128 x 36], B bf16 2 x [128 x 40]
#define P1_ASTG (128*36)
#define P1_BSTG (128*40)
#define P1_SMEM (2*P1_ASTG*4 + 2*P1_BSTG*2)      // 57344

// ---------------- scratch (static device globals; no allocation) ----------------
__device__ float g_Xp[NINS*TOK*G4];      // gate-interleaved token input projections
__device__ float g_H[NINS*HID];
__device__ float g_H2[NINS*HID];
__device__ float g_Gx[NINS*G4];          // gate-interleaved
__device__ float g_Hi[NINS*HID];
__device__ float g_Ci[NINS*HID];
__device__ float g_h0[KROWS*HID];
__device__ float g_c0[KROWS*HID];
__device__ __nv_bfloat16 g_WhhTokB[G4*HID];  // gate-interleaved rows, bf16
__device__ __nv_bfloat16 g_WihTokB[G4*EMB];  // gate-interleaved rows, bf16
__device__ float g_WhhInsP[G4*HID];      // gate-interleaved, tf32-rounded fp32
__device__ float g_WihInsP[G4*HID];
__device__ float g_biasTokP[G4];
__device__ float g_biasInsP[G4];
__device__ unsigned char g_pval[NINS*PAR];
__device__ int   g_appears[NINS];
__device__ float g_partial[64*HID];
__device__ unsigned int g_barM[16];      // per m-group barriers for phase2

// ---------------- helpers ----------------
__device__ __forceinline__ uint32_t cvt_tf32(float v) {
    uint32_t r;
    asm("cvt.rna.tf32.f32 %0, %1;" : "=r"(r) : "f"(v));
    return r;
}
__device__ __forceinline__ uint32_t pack_bf16x2(float lo, float hi) {
    uint32_t r;
    asm("cvt.rn.bf16x2.f32 %0, %1, %2;" : "=r"(r) : "f"(hi), "f"(lo));
    return r;
}
__device__ __forceinline__ void mma_tf32(float* c, uint32_t a0, uint32_t a1,
                                         uint32_t a2, uint32_t a3,
                                         uint32_t b0, uint32_t b1) {
    asm("mma.sync.aligned.m16n8k8.row.col.f32.tf32.tf32.f32 "
        "{%0,%1,%2,%3}, {%4,%5,%6,%7}, {%8,%9}, {%0,%1,%2,%3};"
        : "+f"(c[0]), "+f"(c[1]), "+f"(c[2]), "+f"(c[3])
        : "r"(a0), "r"(a1), "r"(a2), "r"(a3), "r"(b0), "r"(b1));
}
__device__ __forceinline__ void mma_bf16(float* c, uint32_t a0, uint32_t a1,
                                         uint32_t a2, uint32_t a3,
                                         uint32_t b0, uint32_t b1) {
    asm("mma.sync.aligned.m16n8k16.row.col.f32.bf16.bf16.f32 "
        "{%0,%1,%2,%3}, {%4,%5,%6,%7}, {%8,%9}, {%0,%1,%2,%3};"
        : "+f"(c[0]), "+f"(c[1]), "+f"(c[2]), "+f"(c[3])
        : "r"(a0), "r"(a1), "r"(a2), "r"(a3), "r"(b0), "r"(b1));
}
__device__ __forceinline__ void cp_async16(void* smem, const void* gmem) {
    uint32_t s = (uint32_t)__cvta_generic_to_shared(smem);
    asm volatile("cp.async.cg.shared.global [%0], [%1], 16;\n" :: "r"(s), "l"(gmem));
}

// ---------------- grid barrier (proven: fence + atomicAdd poll) ----------------
__device__ __forceinline__ void grid_sync(unsigned int* bar, unsigned int target) {
    __threadfence();
    __syncthreads();
    if (threadIdx.x == 0) {
        atomicAdd(bar, 1u);
        while (atomicAdd(bar, 0u) < target) { __nanosleep(32); }
    }
    __syncthreads();
    __threadfence();
}

// ---------------- prep: pval normalize + appears + barrier reset ----------------
__global__ void prep_kernel(const unsigned char* __restrict__ pv_raw,
                            const int* __restrict__ pidx)
{
    __shared__ int s_hi, s_b0;
    __shared__ int s_app[NINS];
    int tid = threadIdx.x;
    if (tid < 16) g_barM[tid] = 0u;
    int hi = 0, b0 = 0;
    for (int i = 256 + tid; i < 4096; i += 256) {
        hi |= pv_raw[4*i+1] | pv_raw[4*i+2] | pv_raw[4*i+3];
        b0 |= pv_raw[4*i+0];
    }
    if (tid == 0) { s_hi = 0; s_b0 = 0; }
    __syncthreads();
    if (hi) atomicOr(&s_hi, 1);
    if (b0) atomicOr(&s_b0, 1);
    __syncthreads();
    int mode = (s_hi == 0) ? 0 : (s_b0 == 0 ? 1 : 2);
    for (int i = tid; i < NINS*PAR; i += 256) {
        unsigned char v;
        if (mode == 0)      v = (((const int*)pv_raw)[i]   != 0);
        else if (mode == 1) v = (((const float*)pv_raw)[i] != 0.0f);
        else                v = (pv_raw[i] != 0);
        g_pval[i] = v;
    }
    for (int i = tid; i < NINS; i += 256) s_app[i] = 0;
    __syncthreads();
    for (int i = tid; i < NINS*PAR; i += 256) {
        if (g_pval[i]) atomicAdd(&s_app[pidx[i]], 1);
    }
    __syncthreads();
    for (int i = tid; i < NINS; i += 256) g_appears[i] = s_app[i];
}

// ---------------- merged weight/bias prep ----------------
__global__ void permAll_kernel(const float* __restrict__ Whh_tok,
                               const float* __restrict__ Whh_ins,
                               const float* __restrict__ Wih_tok,
                               const float* __restrict__ Wih_ins,
                               const float* __restrict__ bih_tok,
                               const float* __restrict__ bhh_tok,
                               const float* __restrict__ bih_ins,
                               const float* __restrict__ bhh_ins)
{
    int np = blockIdx.x;
    int n  = (np & 3) * HID + (np >> 2);
    int c  = threadIdx.x;
    g_WhhTokB[(size_t)np * HID + c] = __float2bfloat16_rn(Whh_tok[(size_t)n * HID + c]);
    g_WhhInsP[(size_t)np * HID + c] = __uint_as_float(cvt_tf32(Whh_ins[(size_t)n * HID + c]));
    g_WihInsP[(size_t)np * HID + c] = __uint_as_float(cvt_tf32(Wih_ins[(size_t)n * HID + c]));
    g_WihTokB[(size_t)np * EMB + c]       = __float2bfloat16_rn(Wih_tok[(size_t)n * EMB + c]);
    g_WihTokB[(size_t)np * EMB + 256 + c] = __float2bfloat16_rn(Wih_tok[(size_t)n * EMB + 256 + c]);
    if (c == 0) {
        g_biasTokP[np] = bih_tok[n] + bhh_tok[n];
        g_biasInsP[np] = bih_ins[n] + bhh_ins[n];
    }
}

// ============================================================================
// tf32 tile GEMM (kept for phase-3a / level kernels)
// ============================================================================
template<int KDIM>
__device__ __forceinline__ void tile_gemm(
    const float* __restrict__ A, const float* __restrict__ B,
    int bm, int bn, float (&acc)[4][4][4], float* As, float* Bs)
{
    const int tid  = threadIdx.x;
    const int lane = tid & 31;
    const int warp = tid >> 5;
    const int wm = (warp >> 2) * 64;
    const int wn = (warp & 3) * 32;
    const int g   = lane >> 2;
    const int tig = lane & 3;
    const int NT = KDIM / 16;

#pragma unroll
    for (int u = 0; u < 2; u++) {
        int idx = u * 256 + tid;
        int r = idx >> 2, c4 = idx & 3;
        cp_async16(As + r * T_PAD + c4 * 4, A + (size_t)(bm + r) * KDIM + c4 * 4);
        cp_async16(Bs + r * T_PAD + c4 * 4, B + (size_t)(bn + r) * KDIM + c4 * 4);
    }
    asm volatile("cp.async.commit_group;\n");

    for (int kt = 0; kt < NT; kt++) {
        int cur = kt & 1;
        if (kt + 1 < NT) {
            int nxt = (kt + 1) & 1;
            const float* Ap = A + (size_t)bm * KDIM + (kt + 1) * 16;
            const float* Bp = B + (size_t)bn * KDIM + (kt + 1) * 16;
#pragma unroll
            for (int u = 0; u < 2; u++) {
                int idx = u * 256 + tid;
                int r = idx >> 2, c4 = idx & 3;
                cp_async16(As + nxt * 128 * T_PAD + r * T_PAD + c4 * 4,
                           Ap + (size_t)r * KDIM + c4 * 4);
                cp_async16(Bs + nxt * 128 * T_PAD + r * T_PAD + c4 * 4,
                           Bp + (size_t)r * KDIM + c4 * 4);
            }
            asm volatile("cp.async.commit_group;\n");
            asm volatile("cp.async.wait_group 1;\n");
        } else {
            asm volatile("cp.async.wait_group 0;\n");
        }
        __syncthreads();

        const float* Asb = As + cur * 128 * T_PAD;
        const float* Bsb = Bs + cur * 128 * T_PAD;
#pragma unroll
        for (int ks = 0; ks < 2; ks++) {
            const int k0 = ks * 8;
            uint32_t bf[4][2];
#pragma unroll
            for (int ni = 0; ni < 4; ni++) {
                bf[ni][0] = __float_as_uint(Bsb[(wn + ni*8 + g) * T_PAD + k0 + tig]);
                bf[ni][1] = __float_as_uint(Bsb[(wn + ni*8 + g) * T_PAD + k0 + tig + 4]);
            }
            uint32_t af[4][4];
#pragma unroll
            for (int mi = 0; mi < 4; mi++) {
                int r0 = (wm + mi*16 + g) * T_PAD + k0;
                int r1 = (wm + mi*16 + 8 + g) * T_PAD + k0;
                af[mi][0] = cvt_tf32(Asb[r0 + tig]);
                af[mi][1] = cvt_tf32(Asb[r1 + tig]);
                af[mi][2] = cvt_tf32(Asb[r0 + tig + 4]);
                af[mi][3] = cvt_tf32(Asb[r1 + tig + 4]);
            }
#pragma unroll
            for (int mi = 0; mi < 4; mi++)
#pragma unroll
                for (int ni = 0; ni < 4; ni++)
                    mma_tf32(acc[mi][ni], af[mi][0], af[mi][1], af[mi][2], af[mi][3],
                             bf[ni][0], bf[ni][1]);
        }
        __syncthreads();
    }
}

// fused LSTM epilogue (global C); Add gate-interleaved -> one float4/thread
__device__ __forceinline__ void fuse_epilogue(
    float (&acc)[4][4][4], int bm, int bn,
    const float* __restrict__ Add, long addStride,
    const float* __restrict__ Cprev,
    float* __restrict__ Hout, float* __restrict__ Cstate)
{
    const int lane = threadIdx.x & 31;
    const int warp = threadIdx.x >> 5;
    const int wm = (warp >> 2) * 64;
    const int wn = (warp & 3) * 32;
    const int g   = lane >> 2;
    const int tig = lane & 3;
#pragma unroll
    for (int mi = 0; mi < 4; mi++) {
#pragma unroll
        for (int ni = 0; ni < 4; ni++) {
            float c0 = acc[mi][ni][0], c1 = acc[mi][ni][1];
            float c2 = acc[mi][ni][2], c3 = acc[mi][ni][3];
            float x0 = __shfl_xor_sync(0xffffffffu, c0, 1);
            float x1 = __shfl_xor_sync(0xffffffffu, c1, 1);
            float x2 = __shfl_xor_sync(0xffffffffu, c2, 1);
            float x3 = __shfl_xor_sync(0xffffffffu, c3, 1);
            int q = tig >> 1;
            int h = (bn + wn + ni*8 + q*4) >> 2;
            int row;
            float gi, gf, gg, go;
            if ((tig & 1) == 0) {
                row = bm + wm + mi*16 + g;
                gi = c0; gf = c1; gg = x0; go = x1;
            } else {
                row = bm + wm + mi*16 + 8 + g;
                gi = x2; gf = x3; gg = c2; go = c3;
            }
            const float4 ad4 = *(const float4*)(Add + (size_t)row * addStride + 4*h);
            gi += ad4.x;
            gf += ad4.y;
            gg += ad4.z;
            go += ad4.w;
            float c = Cprev ? Cprev[(size_t)row * HID + h] : 0.0f;
            float si = 1.0f / (1.0f + expf(-gi));
            float sf = 1.0f / (1.0f + expf(-gf));
            float so = 1.0f / (1.0f + expf(-go));
            float cn = sf * c + si * tanhf(gg);
            float hn = so * tanhf(cn);
            Cstate[(size_t)row * HID + h] = cn;
            Hout[(size_t)row * HID + h]   = hn;
        }
    }
}

// ============================================================================
// Phase-1 bf16 GEMM: C[M,1024] = A_f32[M,512] @ B_bf16[1024,512]^T + bias
// A loaded fp32, packed to bf16x2 in-loop. Tile 128x128, chunks of K=32.
// ============================================================================
__global__ __launch_bounds__(256, 2) void p1_bf16_kernel(
    const float* __restrict__ A, float* __restrict__ Cout,
    const float* __restrict__ bias)
{
    extern __shared__ float dsm[];
    float* As = dsm;                                   // 2 x [128 x 36] fp32
    __nv_bfloat16* Bs = (__nv_bfloat16*)(dsm + 2*P1_ASTG);  // 2 x [128 x 40] bf16

    const int KDIM = EMB;
    const int tid  = threadIdx.x;
    const int lane = tid & 31;
    const int warp = tid >> 5;
    const int wm = (warp >> 2) * 64;
    const int wn = (warp & 3) * 32;
    const int g   = lane >> 2;
    const int tig = lane & 3;
    const int bm = blockIdx.y * 128;
    const int bn = blockIdx.x * 128;
    const int NT = KDIM / 32;   // 16 chunks

    float acc[4][4][4];
#pragma unroll
    for (int mi = 0; mi < 4; mi++)
#pragma unroll
        for (int ni = 0; ni < 4; ni++)
#pragma unroll
            for (int r = 0; r < 4; r++) acc[mi][ni][r] = 0.0f;

    // prefetch chunk 0
#pragma unroll
    for (int u = 0; u < 4; u++) {          // A: 128 x 8 units
        int idx = u * 256 + tid;
        int r = idx >> 3, c4 = idx & 7;
        cp_async16(As + r * 36 + c4 * 4, A + (size_t)(bm + r) * KDIM + c4 * 4);
    }
#pragma unroll
    for (int u = 0; u < 2; u++) {          // B: 128 x 4 units (16B = 8 bf16)
        int idx = u * 256 + tid;
        int r = idx >> 2, c8 = idx & 3;
        cp_async16(Bs + r * 40 + c8 * 8, g_WihTokB + (size_t)(bn + r) * KDIM + c8 * 8);
    }
    asm volatile("cp.async.commit_group;\n");

    for (int kt = 0; kt < NT; kt++) {
        int cur = kt & 1;
        if (kt + 1 < NT) {
            int nxt = (kt + 1) & 1;
            const float* Ap = A + (size_t)bm * KDIM + (kt + 1) * 32;
            const __nv_bfloat16* Bp = g_WihTokB + (size_t)bn * KDIM + (kt + 1) * 32;
#pragma unroll
            for (int u = 0; u < 4; u++) {
                int idx = u * 256 + tid;
                int r = idx >> 3, c4 = idx & 7;
                cp_async16(As + nxt * P1_ASTG + r * 36 + c4 * 4,
                           Ap + (size_t)r * KDIM + c4 * 4);
            }
#pragma unroll
            for (int u = 0; u < 2; u++) {
                int idx = u * 256 + tid;
                int r = idx >> 2, c8 = idx & 3;
                cp_async16(Bs + nxt * P1_BSTG + r * 40 + c8 * 8,
                           Bp + (size_t)r * KDIM + c8 * 8);
            }
            asm volatile("cp.async.commit_group;\n");
            asm volatile("cp.async.wait_group 1;\n");
        } else {
            asm volatile("cp.async.wait_group 0;\n");
        }
        __syncthreads();

        const float* Asb = As + cur * P1_ASTG;
        const __nv_bfloat16* Bsb = Bs + cur * P1_BSTG;
#pragma unroll
        for (int ks = 0; ks < 2; ks++) {
            const int k0 = ks * 16;
            uint32_t b0[4], b1[4];
#pragma unroll
            for (int ni = 0; ni < 4; ni++) {
                const __nv_bfloat16* bp = Bsb + (wn + ni*8 + g) * 40 + k0;
                b0[ni] = *(const uint32_t*)(bp + 2*tig);
                b1[ni] = *(const uint32_t*)(bp + 8 + 2*tig);
            }
            uint32_t a0[4], a1[4], a2[4], a3[4];
#pragma unroll
            for (int mi = 0; mi < 4; mi++) {
                const float* r0p = Asb + (wm + mi*16 + g) * 36 + k0;
                const float* r1p = Asb + (wm + mi*16 + 8 + g) * 36 + k0;
                a0[mi] = pack_bf16x2(r0p[2*tig],     r0p[2*tig + 1]);
                a1[mi] = pack_bf16x2(r1p[2*tig],     r1p[2*tig + 1]);
                a2[mi] = pack_bf16x2(r0p[8 + 2*tig], r0p[9 + 2*tig]);
                a3[mi] = pack_bf16x2(r1p[8 + 2*tig], r1p[9 + 2*tig]);
            }
#pragma unroll
            for (int mi = 0; mi < 4; mi++)
#pragma unroll
                for (int ni = 0; ni < 4; ni++)
                    mma_bf16(acc[mi][ni], a0[mi], a1[mi], a2[mi], a3[mi], b0[ni], b1[ni]);
        }
        __syncthreads();
    }

#pragma unroll
    for (int mi = 0; mi < 4; mi++) {
        int r0 = bm + wm + mi*16 + g;
        int r1 = r0 + 8;
#pragma unroll
        for (int ni = 0; ni < 4; ni++) {
            int c = bn + wn + ni*8 + tig*2;
            float bb0 = bias[c];
            float bb1 = bias[c+1];
            float2 v0 = make_float2(acc[mi][ni][0] + bb0, acc[mi][ni][1] + bb1);
            float2 v1 = make_float2(acc[mi][ni][2] + bb0, acc[mi][ni][3] + bb1);
            *(float2*)(Cout + (size_t)r0 * G4 + c) = v0;
            *(float2*)(Cout + (size_t)r1 * G4 + c) = v1;
        }
    }
}

// ============================================================================
// Phase-2 persistent: 16 token-LSTM steps, 128 blocks, m-group barriers.
// A (H, fp32) fully resident per step; B (Whh bf16) resident for all steps.
// One __syncthreads per step GEMM; C state in registers.
// ============================================================================
__global__ __launch_bounds__(256) void phase2_kernel()
{
    extern __shared__ float dsm[];
    float* Ares = dsm;                                   // [128 x 260] fp32
    __nv_bfloat16* Bres = (__nv_bfloat16*)(dsm + 128*260); // [128 x 264] bf16

    const int tid  = threadIdx.x;
    const int lane = tid & 31;
    const int warp = tid >> 5;
    const int wm = (warp >> 2) * 64;
    const int wn = (warp & 3) * 32;
    const int g   = lane >> 2;
    const int tig = lane & 3;
    const int mg = blockIdx.x >> 3;
    const int bm = mg * 128;
    const int bn = (blockIdx.x & 7) * 128;

    // load resident B once: 128 rows x 256 bf16
#pragma unroll
    for (int u = 0; u < 16; u++) {
        int idx = u * 256 + tid;
        int r = idx >> 5, c8 = idx & 31;
        cp_async16(Bres + r * 264 + c8 * 8, g_WhhTokB + (size_t)(bn + r) * HID + c8 * 8);
    }
    asm volatile("cp.async.commit_group;\n");
    asm volatile("cp.async.wait_group 0;\n");
    __syncthreads();

    float cst[4][4];
#pragma unroll
    for (int mi = 0; mi < 4; mi++)
#pragma unroll
        for (int ni = 0; ni < 4; ni++) cst[mi][ni] = 0.0f;

    for (int t = 0; t < TOK; t++) {
        float acc[4][4][4];
#pragma unroll
        for (int mi = 0; mi < 4; mi++)
#pragma unroll
            for (int ni = 0; ni < 4; ni++)
#pragma unroll
                for (int r = 0; r < 4; r++) acc[mi][ni][r] = 0.0f;

        const float* Aglob = (t & 1) ? g_H2 : g_H;
        float* Hdst = (t & 1) ? g_H : g_H2;

        if (t > 0) {
            // bulk-load A tile: 128 rows x 256 fp32
#pragma unroll
            for (int u = 0; u < 32; u++) {
                int idx = u * 256 + tid;
                int r = idx >> 6, c4 = idx & 63;
                cp_async16(Ares + r * 260 + c4 * 4, Aglob + (size_t)(bm + r) * HID + c4 * 4);
            }
            asm volatile("cp.async.commit_group;\n");
            asm volatile("cp.async.wait_group 0;\n");
            __syncthreads();

            // sync-free K loop: 16 k16 steps
#pragma unroll
            for (int kt = 0; kt < 16; kt++) {
                const int k0 = kt * 16;
                uint32_t b0[4], b1[4];
#pragma unroll
                for (int ni = 0; ni < 4; ni++) {
                    const __nv_bfloat16* bp = Bres + (wn + ni*8 + g) * 264 + k0;
                    b0[ni] = *(const uint32_t*)(bp + 2*tig);
                    b1[ni] = *(const uint32_t*)(bp + 8 + 2*tig);
                }
                uint32_t a0[4], a1[4], a2[4], a3[4];
#pragma unroll
                for (int mi = 0; mi < 4; mi++) {
                    const float* r0p = Ares + (wm + mi*16 + g) * 260 + k0;
                    const float* r1p = Ares + (wm + mi*16 + 8 + g) * 260 + k0;
                    a0[mi] = pack_bf16x2(r0p[2*tig],     r0p[2*tig + 1]);
                    a1[mi] = pack_bf16x2(r1p[2*tig],     r1p[2*tig + 1]);
                    a2[mi] = pack_bf16x2(r0p[8 + 2*tig], r0p[9 + 2*tig]);
                    a3[mi] = pack_bf16x2(r1p[8 + 2*tig], r1p[9 + 2*tig]);
                }
#pragma unroll
                for (int mi = 0; mi < 4; mi++)
#pragma unroll
                    for (int ni = 0; ni < 4; ni++)
                        mma_bf16(acc[mi][ni], a0[mi], a1[mi], a2[mi], a3[mi], b0[ni], b1[ni]);
            }
        }

        // epilogue: register C, gate-interleaved Xp float4, write H only
#pragma unroll
        for (int mi = 0; mi < 4; mi++) {
#pragma unroll
            for (int ni = 0; ni < 4; ni++) {
                float c0 = acc[mi][ni][0], c1 = acc[mi][ni][1];
                float c2 = acc[mi][ni][2], c3 = acc[mi][ni][3];
                float x0 = __shfl_xor_sync(0xffffffffu, c0, 1);
                float x1 = __shfl_xor_sync(0xffffffffu, c1, 1);
                float x2 = __shfl_xor_sync(0xffffffffu, c2, 1);
                float x3 = __shfl_xor_sync(0xffffffffu, c3, 1);
                int q = tig >> 1;
                int h = (bn + wn + ni*8 + q*4) >> 2;
                int row;
                float gi, gf, gg, go;
                if ((tig & 1) == 0) {
                    row = bm + wm + mi*16 + g;
                    gi = c0; gf = c1; gg = x0; go = x1;
                } else {
                    row = bm + wm + mi*16 + 8 + g;
                    gi = x2; gf = x3; gg = c2; go = c3;
                }
                const float4 ad4 = *(const float4*)(g_Xp + ((size_t)row * TOK + t) * G4 + 4*h);
                gi += ad4.x;
                gf += ad4.y;
                gg += ad4.z;
                go += ad4.w;
                float c = cst[mi][ni];
                float si = 1.0f / (1.0f + expf(-gi));
                float sf = 1.0f / (1.0f + expf(-gf));
                float so = 1.0f / (1.0f + expf(-go));
                float cn = sf * c + si * tanhf(gg);
                float hn = so * tanhf(cn);
                cst[mi][ni] = cn;
                Hdst[(size_t)row * HID + h] = hn;
            }
        }

        if (t + 1 < TOK)
            grid_sync(&g_barM[mg], 8u * (unsigned)(t + 1));
    }
}

// ============================================================================
// Plain tf32 GEMM kernel (phase-3a Gx): C = A@B^T + bias (permuted)
// ============================================================================
template<int KDIM>
__global__ __launch_bounds__(256, 2) void mma_plain_kernel(
    const float* __restrict__ A, const float* __restrict__ B,
    float* __restrict__ Cout, const float* __restrict__ bias)
{
    __shared__ float As[2*128*T_PAD];
    __shared__ float Bs[2*128*T_PAD];
    const int bm = blockIdx.y * 128;
    const int bn = blockIdx.x * 128;
    const int lane = threadIdx.x & 31;
    const int warp = threadIdx.x >> 5;
    const int wm = (warp >> 2) * 64;
    const int wn = (warp & 3) * 32;
    const int g   = lane >> 2;
    const int tig = lane & 3;

    float acc[4][4][4];
#pragma unroll
    for (int mi = 0; mi < 4; mi++)
#pragma unroll
        for (int ni = 0; ni < 4; ni++)
#pragma unroll
            for (int r = 0; r < 4; r++) acc[mi][ni][r] = 0.0f;

    tile_gemm<KDIM>(A, B, bm, bn, acc, As, Bs);

#pragma unroll
    for (int mi = 0; mi < 4; mi++) {
        int r0 = bm + wm + mi*16 + g;
        int r1 = r0 + 8;
#pragma unroll
        for (int ni = 0; ni < 4; ni++) {
            int c = bn + wn + ni*8 + tig*2;
            float bb0 = bias[c];
            float bb1 = bias[c+1];
            float2 v0 = make_float2(acc[mi][ni][0] + bb0, acc[mi][ni][1] + bb1);
            float2 v1 = make_float2(acc[mi][ni][2] + bb0, acc[mi][ni][3] + bb1);
            *(float2*)(Cout + (size_t)r0 * G4 + c) = v0;
            *(float2*)(Cout + (size_t)r1 * G4 + c) = v1;
        }
    }
}

// ---------------- per-level parent gather (max combine) ----------------
__global__ void gather_kernel(const int* __restrict__ pidx, int l)
{
    int r   = blockIdx.x;
    int row = l * KROWS + r;
    int h   = threadIdx.x;
    __shared__ int sp[PAR];
    __shared__ int sv[PAR];
    if (h < PAR) {
        sp[h] = pidx[row*PAR + h];
        sv[h] = g_pval[row*PAR + h];
    }
    __syncthreads();
    float mh = -1e30f, mc = -1e30f;
    int has = 0;
#pragma unroll
    for (int p = 0; p < PAR; p++) {
        if (sv[p]) {
            has = 1;
            mh = fmaxf(mh, g_Hi[(size_t)sp[p]*HID + h]);
            mc = fmaxf(mc, g_Ci[(size_t)sp[p]*HID + h]);
        }
    }
    g_h0[r*HID + h] = has ? mh : 0.0f;
    g_c0[r*HID + h] = has ? mc : 0.0f;
}

// per-level fused GEMM+LSTM (8 blocks, M=128)
__global__ __launch_bounds__(256, 2) void level_kernel(int l)
{
    __shared__ float As[2*128*T_PAD];
    __shared__ float Bs[2*128*T_PAD];
    const int bn = blockIdx.x * 128;
    float acc[4][4][4];
#pragma unroll
    for (int mi = 0; mi < 4; mi++)
#pragma unroll
        for (int ni = 0; ni < 4; ni++)
#pragma unroll
            for (int r = 0; r < 4; r++) acc[mi][ni][r] = 0.0f;

    tile_gemm<HID>(g_h0, g_WhhInsP, 0, bn, acc, As, Bs);
    fuse_epilogue(acc, 0, bn, g_Gx + (size_t)l * KROWS * G4, (long)G4,
                  g_c0, g_Hi + (size_t)l * KROWS * HID, g_Ci + (size_t)l * KROWS * HID);
}

// ---------------- final: masked max over roots, then dot with Wlin ----------------
__global__ void final1_kernel()
{
    int b = blockIdx.x;
    int h = threadIdx.x;
    float m = -1e30f;
    for (int r = b*32; r < b*32 + 32; r++)
        if (g_appears[r] == 0) m = fmaxf(m, g_Hi[(size_t)r*HID + h]);
    g_partial[b*HID + h] = m;
}

__global__ void final2_kernel(const float* __restrict__ Wlin,
                              const float* __restrict__ blin,
                              float* __restrict__ out)
{
    int h = threadIdx.x;
    float m = -1e30f;
    for (int b = 0; b < 64; b++) m = fmaxf(m, g_partial[b*HID + h]);
    float v = m * Wlin[h];
    __shared__ float s[256];
    s[h] = v;
    __syncthreads();
    for (int st = 128; st > 0; st >>= 1) {
        if (h < st) s[h] += s[h + st];
        __syncthreads();
    }
    if (h == 0) out[0] = s[0] + blin[0];
}

// ---------------- launch ----------------
extern "C" void kernel_launch(void* const* d_in, const int* in_sizes, int n_in,
                              void* d_out, int out_size)
{
    const float* tokens   = (const float*)d_in[0];
    const int*   pidx     = (const int*)  d_in[1];
    const unsigned char* pval = (const unsigned char*)d_in[2];
    const float* Wih_tok  = (const float*)d_in[3];
    const float* Whh_tok  = (const float*)d_in[4];
    const float* bih_tok  = (const float*)d_in[5];
    const float* bhh_tok  = (const float*)d_in[6];
    const float* Wih_ins  = (const float*)d_in[7];
    const float* Whh_ins  = (const float*)d_in[8];
    const float* bih_ins  = (const float*)d_in[9];
    const float* bhh_ins  = (const float*)d_in[10];
    const float* Wlin     = (const float*)d_in[11];
    const float* blin     = (const float*)d_in[12];
    float* out = (float*)d_out;

    float *pXp, *pH, *pGx, *pWihInsP, *pBT, *pBI;
    cudaGetSymbolAddress((void**)&pXp,      g_Xp);
    cudaGetSymbolAddress((void**)&pH,       g_H);
    cudaGetSymbolAddress((void**)&pGx,      g_Gx);
    cudaGetSymbolAddress((void**)&pWihInsP, g_WihInsP);
    cudaGetSymbolAddress((void**)&pBT,      g_biasTokP);
    cudaGetSymbolAddress((void**)&pBI,      g_biasInsP);

    cudaFuncSetAttribute(phase2_kernel,  cudaFuncAttributeMaxDynamicSharedMemorySize, P2_SMEM);
    cudaFuncSetAttribute(p1_bf16_kernel, cudaFuncAttributeMaxDynamicSharedMemorySize, P1_SMEM);

    prep_kernel<<<1, 256>>>(pval, pidx);
    permAll_kernel<<<G4, 256>>>(Whh_tok, Whh_ins, Wih_tok, Wih_ins,
                                bih_tok, bhh_tok, bih_ins, bhh_ins);

    // Phase 1: Xp (gate-interleaved) = tokens @ WihTokB^T + biasTokP  (bf16 MMA)
    p1_bf16_kernel<<<dim3(8, 256), 256, P1_SMEM>>>(tokens, pXp, pBT);

    // Phase 2: persistent token-LSTM recurrence (final hidden lands in g_H)
    phase2_kernel<<<128, 256, P2_SMEM>>>();

    // Phase 3a: Gx (gate-interleaved) = ins_embed @ WihInsP^T + biasInsP (tf32)
    mma_plain_kernel<HID><<<dim3(8, 16), 256>>>(pH, pWihInsP, pGx, pBI);

    // Phase 3b: per-level gather (wide) + fused GEMM+LSTM (tf32)
    for (int l = 0; l < LEVELS; l++) {
        gather_kernel<<<KROWS, HID>>>(pidx, l);
        level_kernel<<<8, 256>>>(l);
    }

    final1_kernel<<<64, 256>>>();
    final2_kernel<<<1, 256>>>(Wlin, blin, out);
}

// round 16
// speedup vs baseline: 1.3090x; 1.1140x over previous
#include <cuda_runtime.h>
#include <cuda_fp16.h>
#include <math.h>
#include <stdint.h>

#define NINS   2048
#define TOK    16
#define EMB    512
#define HID    256
#define G4     (4*HID)      // 1024
#define PAR    8
#define LEVELS 16
#define KROWS  (NINS/LEVELS) // 128
#define T_PAD  20
// phase2 dynamic smem: A fp16 [128x264] + B fp16 [128x264] + Xp stage fp32 [128x132]
#define P2_SMEM (128*264*2 + 128*264*2 + 128*132*4)   // 202752
// phase1 dynamic smem: A fp32 2 x [128 x 36], B fp16 2 x [128 x 40]
#define P1_ASTG (128*36)
#define P1_BSTG (128*40)
#define P1_SMEM (2*P1_ASTG*4 + 2*P1_BSTG*2)           // 57344

// ---------------- scratch (static device globals; no allocation) ----------------
__device__ float g_Xp[NINS*TOK*G4];      // gate-interleaved token input projections
__device__ float g_H[NINS*HID];          // final token-LSTM hidden (fp32, for phase-3a)
__device__ __half g_Hf[NINS*HID];        // fp16 H ping
__device__ __half g_Hf2[NINS*HID];       // fp16 H pong
__device__ float g_Gx[NINS*G4];          // gate-interleaved
__device__ float g_Hi[NINS*HID];
__device__ float g_Ci[NINS*HID];
__device__ float g_h0[KROWS*HID];
__device__ float g_c0[KROWS*HID];
__device__ __half g_WhhTokH[G4*HID];     // gate-interleaved rows, fp16
__device__ __half g_WihTokH[G4*EMB];     // gate-interleaved rows, fp16
__device__ float g_WhhInsP[G4*HID];      // gate-interleaved, tf32-rounded fp32
__device__ float g_WihInsP[G4*HID];
__device__ float g_biasTokP[G4];
__device__ float g_biasInsP[G4];
__device__ unsigned char g_pval[NINS*PAR];
__device__ int   g_appears[NINS];
__device__ float g_partial[64*HID];
__device__ unsigned int g_barM[16];      // per m-group barriers for phase2

// ---------------- helpers ----------------
__device__ __forceinline__ uint32_t cvt_tf32(float v) {
    uint32_t r;
    asm("cvt.rna.tf32.f32 %0, %1;" : "=r"(r) : "f"(v));
    return r;
}
__device__ __forceinline__ uint32_t pack_f16x2(float lo, float hi) {
    uint32_t r;
    asm("cvt.rn.f16x2.f32 %0, %1, %2;" : "=r"(r) : "f"(hi), "f"(lo));
    return r;
}
__device__ __forceinline__ void mma_tf32(float* c, uint32_t a0, uint32_t a1,
                                         uint32_t a2, uint32_t a3,
                                         uint32_t b0, uint32_t b1) {
    asm("mma.sync.aligned.m16n8k8.row.col.f32.tf32.tf32.f32 "
        "{%0,%1,%2,%3}, {%4,%5,%6,%7}, {%8,%9}, {%0,%1,%2,%3};"
        : "+f"(c[0]), "+f"(c[1]), "+f"(c[2]), "+f"(c[3])
        : "r"(a0), "r"(a1), "r"(a2), "r"(a3), "r"(b0), "r"(b1));
}
__device__ __forceinline__ void mma_f16(float* c, uint32_t a0, uint32_t a1,
                                        uint32_t a2, uint32_t a3,
                                        uint32_t b0, uint32_t b1) {
    asm("mma.sync.aligned.m16n8k16.row.col.f32.f16.f16.f32 "
        "{%0,%1,%2,%3}, {%4,%5,%6,%7}, {%8,%9}, {%0,%1,%2,%3};"
        : "+f"(c[0]), "+f"(c[1]), "+f"(c[2]), "+f"(c[3])
        : "r"(a0), "r"(a1), "r"(a2), "r"(a3), "r"(b0), "r"(b1));
}
__device__ __forceinline__ void cp_async16(void* smem, const void* gmem) {
    uint32_t s = (uint32_t)__cvta_generic_to_shared(smem);
    asm volatile("cp.async.cg.shared.global [%0], [%1], 16;\n" :: "r"(s), "l"(gmem));
}

// ---------------- grid barrier (proven: fence + atomicAdd poll) ----------------
__device__ __forceinline__ void grid_sync(unsigned int* bar, unsigned int target) {
    __threadfence();
    __syncthreads();
    if (threadIdx.x == 0) {
        atomicAdd(bar, 1u);
        while (atomicAdd(bar, 0u) < target) { __nanosleep(32); }
    }
    __syncthreads();
    __threadfence();
}

// ---------------- prep: pval normalize + appears + barrier reset ----------------
__global__ void prep_kernel(const unsigned char* __restrict__ pv_raw,
                            const int* __restrict__ pidx)
{
    __shared__ int s_hi, s_b0;
    __shared__ int s_app[NINS];
    int tid = threadIdx.x;
    if (tid < 16) g_barM[tid] = 0u;
    int hi = 0, b0 = 0;
    for (int i = 256 + tid; i < 4096; i += 256) {
        hi |= pv_raw[4*i+1] | pv_raw[4*i+2] | pv_raw[4*i+3];
        b0 |= pv_raw[4*i+0];
    }
    if (tid == 0) { s_hi = 0; s_b0 = 0; }
    __syncthreads();
    if (hi) atomicOr(&s_hi, 1);
    if (b0) atomicOr(&s_b0, 1);
    __syncthreads();
    int mode = (s_hi == 0) ? 0 : (s_b0 == 0 ? 1 : 2);
    for (int i = tid; i < NINS*PAR; i += 256) {
        unsigned char v;
        if (mode == 0)      v = (((const int*)pv_raw)[i]   != 0);
        else if (mode == 1) v = (((const float*)pv_raw)[i] != 0.0f);
        else                v = (pv_raw[i] != 0);
        g_pval[i] = v;
    }
    for (int i = tid; i < NINS; i += 256) s_app[i] = 0;
    __syncthreads();
    for (int i = tid; i < NINS*PAR; i += 256) {
        if (g_pval[i]) atomicAdd(&s_app[pidx[i]], 1);
    }
    __syncthreads();
    for (int i = tid; i < NINS; i += 256) g_appears[i] = s_app[i];
}

// ---------------- merged weight/bias prep ----------------
__global__ void permAll_kernel(const float* __restrict__ Whh_tok,
                               const float* __restrict__ Whh_ins,
                               const float* __restrict__ Wih_tok,
                               const float* __restrict__ Wih_ins,
                               const float* __restrict__ bih_tok,
                               const float* __restrict__ bhh_tok,
                               const float* __restrict__ bih_ins,
                               const float* __restrict__ bhh_ins)
{
    int np = blockIdx.x;
    int n  = (np & 3) * HID + (np >> 2);
    int c  = threadIdx.x;
    g_WhhTokH[(size_t)np * HID + c] = __float2half_rn(Whh_tok[(size_t)n * HID + c]);
    g_WhhInsP[(size_t)np * HID + c] = __uint_as_float(cvt_tf32(Whh_ins[(size_t)n * HID + c]));
    g_WihInsP[(size_t)np * HID + c] = __uint_as_float(cvt_tf32(Wih_ins[(size_t)n * HID + c]));
    g_WihTokH[(size_t)np * EMB + c]       = __float2half_rn(Wih_tok[(size_t)n * EMB + c]);
    g_WihTokH[(size_t)np * EMB + 256 + c] = __float2half_rn(Wih_tok[(size_t)n * EMB + 256 + c]);
    if (c == 0) {
        g_biasTokP[np] = bih_tok[n] + bhh_tok[n];
        g_biasInsP[np] = bih_ins[n] + bhh_ins[n];
    }
}

// ============================================================================
// tf32 tile GEMM (phase-3a / level kernels)
// ============================================================================
template<int KDIM>
__device__ __forceinline__ void tile_gemm(
    const float* __restrict__ A, const float* __restrict__ B,
    int bm, int bn, float (&acc)[4][4][4], float* As, float* Bs)
{
    const int tid  = threadIdx.x;
    const int lane = tid & 31;
    const int warp = tid >> 5;
    const int wm = (warp >> 2) * 64;
    const int wn = (warp & 3) * 32;
    const int g   = lane >> 2;
    const int tig = lane & 3;
    const int NT = KDIM / 16;

#pragma unroll
    for (int u = 0; u < 2; u++) {
        int idx = u * 256 + tid;
        int r = idx >> 2, c4 = idx & 3;
        cp_async16(As + r * T_PAD + c4 * 4, A + (size_t)(bm + r) * KDIM + c4 * 4);
        cp_async16(Bs + r * T_PAD + c4 * 4, B + (size_t)(bn + r) * KDIM + c4 * 4);
    }
    asm volatile("cp.async.commit_group;\n");

    for (int kt = 0; kt < NT; kt++) {
        int cur = kt & 1;
        if (kt + 1 < NT) {
            int nxt = (kt + 1) & 1;
            const float* Ap = A + (size_t)bm * KDIM + (kt + 1) * 16;
            const float* Bp = B + (size_t)bn * KDIM + (kt + 1) * 16;
#pragma unroll
            for (int u = 0; u < 2; u++) {
                int idx = u * 256 + tid;
                int r = idx >> 2, c4 = idx & 3;
                cp_async16(As + nxt * 128 * T_PAD + r * T_PAD + c4 * 4,
                           Ap + (size_t)r * KDIM + c4 * 4);
                cp_async16(Bs + nxt * 128 * T_PAD + r * T_PAD + c4 * 4,
                           Bp + (size_t)r * KDIM + c4 * 4);
            }
            asm volatile("cp.async.commit_group;\n");
            asm volatile("cp.async.wait_group 1;\n");
        } else {
            asm volatile("cp.async.wait_group 0;\n");
        }
        __syncthreads();

        const float* Asb = As + cur * 128 * T_PAD;
        const float* Bsb = Bs + cur * 128 * T_PAD;
#pragma unroll
        for (int ks = 0; ks < 2; ks++) {
            const int k0 = ks * 8;
            uint32_t bf[4][2];
#pragma unroll
            for (int ni = 0; ni < 4; ni++) {
                bf[ni][0] = __float_as_uint(Bsb[(wn + ni*8 + g) * T_PAD + k0 + tig]);
                bf[ni][1] = __float_as_uint(Bsb[(wn + ni*8 + g) * T_PAD + k0 + tig + 4]);
            }
            uint32_t af[4][4];
#pragma unroll
            for (int mi = 0; mi < 4; mi++) {
                int r0 = (wm + mi*16 + g) * T_PAD + k0;
                int r1 = (wm + mi*16 + 8 + g) * T_PAD + k0;
                af[mi][0] = cvt_tf32(Asb[r0 + tig]);
                af[mi][1] = cvt_tf32(Asb[r1 + tig]);
                af[mi][2] = cvt_tf32(Asb[r0 + tig + 4]);
                af[mi][3] = cvt_tf32(Asb[r1 + tig + 4]);
            }
#pragma unroll
            for (int mi = 0; mi < 4; mi++)
#pragma unroll
                for (int ni = 0; ni < 4; ni++)
                    mma_tf32(acc[mi][ni], af[mi][0], af[mi][1], af[mi][2], af[mi][3],
                             bf[ni][0], bf[ni][1]);
        }
        __syncthreads();
    }
}

// fused LSTM epilogue (global buffers); Add gate-interleaved -> one float4/thread
__device__ __forceinline__ void fuse_epilogue(
    float (&acc)[4][4][4], int bm, int bn,
    const float* __restrict__ Add, long addStride,
    const float* __restrict__ Cprev,
    float* __restrict__ Hout, float* __restrict__ Cstate)
{
    const int lane = threadIdx.x & 31;
    const int warp = threadIdx.x >> 5;
    const int wm = (warp >> 2) * 64;
    const int wn = (warp & 3) * 32;
    const int g   = lane >> 2;
    const int tig = lane & 3;
#pragma unroll
    for (int mi = 0; mi < 4; mi++) {
#pragma unroll
        for (int ni = 0; ni < 4; ni++) {
            float c0 = acc[mi][ni][0], c1 = acc[mi][ni][1];
            float c2 = acc[mi][ni][2], c3 = acc[mi][ni][3];
            float x0 = __shfl_xor_sync(0xffffffffu, c0, 1);
            float x1 = __shfl_xor_sync(0xffffffffu, c1, 1);
            float x2 = __shfl_xor_sync(0xffffffffu, c2, 1);
            float x3 = __shfl_xor_sync(0xffffffffu, c3, 1);
            int q = tig >> 1;
            int h = (bn + wn + ni*8 + q*4) >> 2;
            int row;
            float gi, gf, gg, go;
            if ((tig & 1) == 0) {
                row = bm + wm + mi*16 + g;
                gi = c0; gf = c1; gg = x0; go = x1;
            } else {
                row = bm + wm + mi*16 + 8 + g;
                gi = x2; gf = x3; gg = c2; go = c3;
            }
            const float4 ad4 = *(const float4*)(Add + (size_t)row * addStride + 4*h);
            gi += ad4.x;
            gf += ad4.y;
            gg += ad4.z;
            go += ad4.w;
            float c = Cprev ? Cprev[(size_t)row * HID + h] : 0.0f;
            float si = 1.0f / (1.0f + expf(-gi));
            float sf = 1.0f / (1.0f + expf(-gf));
            float so = 1.0f / (1.0f + expf(-go));
            float cn = sf * c + si * tanhf(gg);
            float hn = so * tanhf(cn);
            Cstate[(size_t)row * HID + h] = cn;
            Hout[(size_t)row * HID + h]   = hn;
        }
    }
}

// ============================================================================
// Phase-1 fp16 GEMM: C[M,1024] = A_f32[M,512] @ B_f16[1024,512]^T + bias
// ============================================================================
__global__ __launch_bounds__(256, 2) void p1_f16_kernel(
    const float* __restrict__ A, float* __restrict__ Cout,
    const float* __restrict__ bias)
{
    extern __shared__ float dsm[];
    float* As = dsm;                                 // 2 x [128 x 36] fp32
    __half* Bs = (__half*)(dsm + 2*P1_ASTG);         // 2 x [128 x 40] fp16

    const int KDIM = EMB;
    const int tid  = threadIdx.x;
    const int lane = tid & 31;
    const int warp = tid >> 5;
    const int wm = (warp >> 2) * 64;
    const int wn = (warp & 3) * 32;
    const int g   = lane >> 2;
    const int tig = lane & 3;
    const int bm = blockIdx.y * 128;
    const int bn = blockIdx.x * 128;
    const int NT = KDIM / 32;   // 16 chunks

    float acc[4][4][4];
#pragma unroll
    for (int mi = 0; mi < 4; mi++)
#pragma unroll
        for (int ni = 0; ni < 4; ni++)
#pragma unroll
            for (int r = 0; r < 4; r++) acc[mi][ni][r] = 0.0f;

#pragma unroll
    for (int u = 0; u < 4; u++) {
        int idx = u * 256 + tid;
        int r = idx >> 3, c4 = idx & 7;
        cp_async16(As + r * 36 + c4 * 4, A + (size_t)(bm + r) * KDIM + c4 * 4);
    }
#pragma unroll
    for (int u = 0; u < 2; u++) {
        int idx = u * 256 + tid;
        int r = idx >> 2, c8 = idx & 3;
        cp_async16(Bs + r * 40 + c8 * 8, g_WihTokH + (size_t)(bn + r) * KDIM + c8 * 8);
    }
    asm volatile("cp.async.commit_group;\n");

    for (int kt = 0; kt < NT; kt++) {
        int cur = kt & 1;
        if (kt + 1 < NT) {
            int nxt = (kt + 1) & 1;
            const float* Ap = A + (size_t)bm * KDIM + (kt + 1) * 32;
            const __half* Bp = g_WihTokH + (size_t)bn * KDIM + (kt + 1) * 32;
#pragma unroll
            for (int u = 0; u < 4; u++) {
                int idx = u * 256 + tid;
                int r = idx >> 3, c4 = idx & 7;
                cp_async16(As + nxt * P1_ASTG + r * 36 + c4 * 4,
                           Ap + (size_t)r * KDIM + c4 * 4);
            }
#pragma unroll
            for (int u = 0; u < 2; u++) {
                int idx = u * 256 + tid;
                int r = idx >> 2, c8 = idx & 3;
                cp_async16(Bs + nxt * P1_BSTG + r * 40 + c8 * 8,
                           Bp + (size_t)r * KDIM + c8 * 8);
            }
            asm volatile("cp.async.commit_group;\n");
            asm volatile("cp.async.wait_group 1;\n");
        } else {
            asm volatile("cp.async.wait_group 0;\n");
        }
        __syncthreads();

        const float* Asb = As + cur * P1_ASTG;
        const __half* Bsb = Bs + cur * P1_BSTG;
#pragma unroll
        for (int ks = 0; ks < 2; ks++) {
            const int k0 = ks * 16;
            uint32_t b0[4], b1[4];
#pragma unroll
            for (int ni = 0; ni < 4; ni++) {
                const __half* bp = Bsb + (wn + ni*8 + g) * 40 + k0;
                b0[ni] = *(const uint32_t*)(bp + 2*tig);
                b1[ni] = *(const uint32_t*)(bp + 8 + 2*tig);
            }
            uint32_t a0[4], a1[4], a2[4], a3[4];
#pragma unroll
            for (int mi = 0; mi < 4; mi++) {
                const float* r0p = Asb + (wm + mi*16 + g) * 36 + k0;
                const float* r1p = Asb + (wm + mi*16 + 8 + g) * 36 + k0;
                a0[mi] = pack_f16x2(r0p[2*tig],     r0p[2*tig + 1]);
                a1[mi] = pack_f16x2(r1p[2*tig],     r1p[2*tig + 1]);
                a2[mi] = pack_f16x2(r0p[8 + 2*tig], r0p[9 + 2*tig]);
                a3[mi] = pack_f16x2(r1p[8 + 2*tig], r1p[9 + 2*tig]);
            }
#pragma unroll
            for (int mi = 0; mi < 4; mi++)
#pragma unroll
                for (int ni = 0; ni < 4; ni++)
                    mma_f16(acc[mi][ni], a0[mi], a1[mi], a2[mi], a3[mi], b0[ni], b1[ni]);
        }
        __syncthreads();
    }

#pragma unroll
    for (int mi = 0; mi < 4; mi++) {
        int r0 = bm + wm + mi*16 + g;
        int r1 = r0 + 8;
#pragma unroll
        for (int ni = 0; ni < 4; ni++) {
            int c = bn + wn + ni*8 + tig*2;
            float bb0 = bias[c];
            float bb1 = bias[c+1];
            float2 v0 = make_float2(acc[mi][ni][0] + bb0, acc[mi][ni][1] + bb1);
            float2 v1 = make_float2(acc[mi][ni][2] + bb0, acc[mi][ni][3] + bb1);
            *(float2*)(Cout + (size_t)r0 * G4 + c) = v0;
            *(float2*)(Cout + (size_t)r1 * G4 + c) = v1;
        }
    }
}

// ============================================================================
// Phase-2 persistent: 16 token-LSTM steps, 128 blocks, m-group barriers.
// H state fp16 in global; A/B fp16 smem-resident; Xp staged via cp.async
// overlapped with the GEMM. C state in registers. One step = 2 syncs.
// ============================================================================
__global__ __launch_bounds__(256) void phase2_kernel()
{
    extern __shared__ float dsm[];
    __half* Ares = (__half*)dsm;                        // [128 x 264] fp16
    __half* Bres = Ares + 128*264;                      // [128 x 264] fp16
    float*  Xst  = (float*)(Bres + 128*264);            // [128 x 132] fp32

    const int tid  = threadIdx.x;
    const int lane = tid & 31;
    const int warp = tid >> 5;
    const int wm = (warp >> 2) * 64;
    const int wn = (warp & 3) * 32;
    const int g   = lane >> 2;
    const int tig = lane & 3;
    const int mg = blockIdx.x >> 3;
    const int bm = mg * 128;
    const int bn = (blockIdx.x & 7) * 128;

    // load resident B once: 128 rows x 256 fp16
#pragma unroll
    for (int u = 0; u < 16; u++) {
        int idx = u * 256 + tid;
        int r = idx >> 5, c8 = idx & 31;
        cp_async16(Bres + r * 264 + c8 * 8, g_WhhTokH + (size_t)(bn + r) * HID + c8 * 8);
    }
    asm volatile("cp.async.commit_group;\n");
    asm volatile("cp.async.wait_group 0;\n");
    __syncthreads();

    float cst[4][4];
#pragma unroll
    for (int mi = 0; mi < 4; mi++)
#pragma unroll
        for (int ni = 0; ni < 4; ni++) cst[mi][ni] = 0.0f;

    for (int t = 0; t < TOK; t++) {
        float acc[4][4][4];
#pragma unroll
        for (int mi = 0; mi < 4; mi++)
#pragma unroll
            for (int ni = 0; ni < 4; ni++)
#pragma unroll
                for (int r = 0; r < 4; r++) acc[mi][ni][r] = 0.0f;

        const __half* Aglob = (t & 1) ? g_Hf2 : g_Hf;
        __half* Hdst = (t & 1) ? g_Hf : g_Hf2;

        // group 1: A tile (only t>0); group 2: Xp stage for this step
        if (t > 0) {
#pragma unroll
            for (int u = 0; u < 16; u++) {
                int idx = u * 256 + tid;
                int r = idx >> 5, c8 = idx & 31;
                cp_async16(Ares + r * 264 + c8 * 8, Aglob + (size_t)(bm + r) * HID + c8 * 8);
            }
            asm volatile("cp.async.commit_group;\n");
        }
#pragma unroll
        for (int u = 0; u < 16; u++) {
            int idx = u * 256 + tid;
            int r = idx >> 5, c4 = idx & 31;
            cp_async16(Xst + r * 132 + c4 * 4,
                       g_Xp + ((size_t)(bm + r) * TOK + t) * G4 + bn + c4 * 4);
        }
        asm volatile("cp.async.commit_group;\n");

        if (t > 0) {
            asm volatile("cp.async.wait_group 1;\n");   // A landed; Xp may pend
            __syncthreads();
            // sync-free K loop: 16 k16 steps, A/B direct fp16 smem loads
#pragma unroll
            for (int kt = 0; kt < 16; kt++) {
                const int k0 = kt * 16;
                uint32_t b0[4], b1[4];
#pragma unroll
                for (int ni = 0; ni < 4; ni++) {
                    const __half* bp = Bres + (wn + ni*8 + g) * 264 + k0;
                    b0[ni] = *(const uint32_t*)(bp + 2*tig);
                    b1[ni] = *(const uint32_t*)(bp + 8 + 2*tig);
                }
                uint32_t a0[4], a1[4], a2[4], a3[4];
#pragma unroll
                for (int mi = 0; mi < 4; mi++) {
                    const __half* r0p = Ares + (wm + mi*16 + g) * 264 + k0;
                    const __half* r1p = Ares + (wm + mi*16 + 8 + g) * 264 + k0;
                    a0[mi] = *(const uint32_t*)(r0p + 2*tig);
                    a1[mi] = *(const uint32_t*)(r1p + 2*tig);
                    a2[mi] = *(const uint32_t*)(r0p + 8 + 2*tig);
                    a3[mi] = *(const uint32_t*)(r1p + 8 + 2*tig);
                }
#pragma unroll
                for (int mi = 0; mi < 4; mi++)
#pragma unroll
                    for (int ni = 0; ni < 4; ni++)
                        mma_f16(acc[mi][ni], a0[mi], a1[mi], a2[mi], a3[mi], b0[ni], b1[ni]);
            }
        }

        asm volatile("cp.async.wait_group 0;\n");       // Xp landed
        __syncthreads();

        // epilogue: register C, Xp from smem stage, H write (fp16; fp32 at t=15)
#pragma unroll
        for (int mi = 0; mi < 4; mi++) {
#pragma unroll
            for (int ni = 0; ni < 4; ni++) {
                float c0 = acc[mi][ni][0], c1 = acc[mi][ni][1];
                float c2 = acc[mi][ni][2], c3 = acc[mi][ni][3];
                float x0 = __shfl_xor_sync(0xffffffffu, c0, 1);
                float x1 = __shfl_xor_sync(0xffffffffu, c1, 1);
                float x2 = __shfl_xor_sync(0xffffffffu, c2, 1);
                float x3 = __shfl_xor_sync(0xffffffffu, c3, 1);
                int q = tig >> 1;
                int h = (bn + wn + ni*8 + q*4) >> 2;
                int row, rl;
                float gi, gf, gg, go;
                if ((tig & 1) == 0) {
                    rl = wm + mi*16 + g;
                    gi = c0; gf = c1; gg = x0; go = x1;
                } else {
                    rl = wm + mi*16 + 8 + g;
                    gi = x2; gf = x3; gg = c2; go = c3;
                }
                row = bm + rl;
                const float4 ad4 = *(const float4*)(Xst + rl * 132 + (wn + ni*8 + q*4));
                gi += ad4.x;
                gf += ad4.y;
                gg += ad4.z;
                go += ad4.w;
                float c = cst[mi][ni];
                float si = 1.0f / (1.0f + expf(-gi));
                float sf = 1.0f / (1.0f + expf(-gf));
                float so = 1.0f / (1.0f + expf(-go));
                float cn = sf * c + si * tanhf(gg);
                float hn = so * tanhf(cn);
                cst[mi][ni] = cn;
                if (t == TOK - 1)
                    g_H[(size_t)row * HID + h] = hn;
                else
                    Hdst[(size_t)row * HID + h] = __float2half_rn(hn);
            }
        }

        if (t + 1 < TOK)
            grid_sync(&g_barM[mg], 8u * (unsigned)(t + 1));
    }
}

// ============================================================================
// Plain tf32 GEMM kernel (phase-3a Gx): C = A@B^T + bias (permuted)
// ============================================================================
template<int KDIM>
__global__ __launch_bounds__(256, 2) void mma_plain_kernel(
    const float* __restrict__ A, const float* __restrict__ B,
    float* __restrict__ Cout, const float* __restrict__ bias)
{
    __shared__ float As[2*128*T_PAD];
    __shared__ float Bs[2*128*T_PAD];
    const int bm = blockIdx.y * 128;
    const int bn = blockIdx.x * 128;
    const int lane = threadIdx.x & 31;
    const int warp = threadIdx.x >> 5;
    const int wm = (warp >> 2) * 64;
    const int wn = (warp & 3) * 32;
    const int g   = lane >> 2;
    const int tig = lane & 3;

    float acc[4][4][4];
#pragma unroll
    for (int mi = 0; mi < 4; mi++)
#pragma unroll
        for (int ni = 0; ni < 4; ni++)
#pragma unroll
            for (int r = 0; r < 4; r++) acc[mi][ni][r] = 0.0f;

    tile_gemm<KDIM>(A, B, bm, bn, acc, As, Bs);

#pragma unroll
    for (int mi = 0; mi < 4; mi++) {
        int r0 = bm + wm + mi*16 + g;
        int r1 = r0 + 8;
#pragma unroll
        for (int ni = 0; ni < 4; ni++) {
            int c = bn + wn + ni*8 + tig*2;
            float bb0 = bias[c];
            float bb1 = bias[c+1];
            float2 v0 = make_float2(acc[mi][ni][0] + bb0, acc[mi][ni][1] + bb1);
            float2 v1 = make_float2(acc[mi][ni][2] + bb0, acc[mi][ni][3] + bb1);
            *(float2*)(Cout + (size_t)r0 * G4 + c) = v0;
            *(float2*)(Cout + (size_t)r1 * G4 + c) = v1;
        }
    }
}

// ---------------- per-level parent gather (max combine) ----------------
__global__ void gather_kernel(const int* __restrict__ pidx, int l)
{
    int r   = blockIdx.x;
    int row = l * KROWS + r;
    int h   = threadIdx.x;
    __shared__ int sp[PAR];
    __shared__ int sv[PAR];
    if (h < PAR) {
        sp[h] = pidx[row*PAR + h];
        sv[h] = g_pval[row*PAR + h];
    }
    __syncthreads();
    float mh = -1e30f, mc = -1e30f;
    int has = 0;
#pragma unroll
    for (int p = 0; p < PAR; p++) {
        if (sv[p]) {
            has = 1;
            mh = fmaxf(mh, g_Hi[(size_t)sp[p]*HID + h]);
            mc = fmaxf(mc, g_Ci[(size_t)sp[p]*HID + h]);
        }
    }
    g_h0[r*HID + h] = has ? mh : 0.0f;
    g_c0[r*HID + h] = has ? mc : 0.0f;
}

// per-level fused GEMM+LSTM (8 blocks, M=128)
__global__ __launch_bounds__(256, 2) void level_kernel(int l)
{
    __shared__ float As[2*128*T_PAD];
    __shared__ float Bs[2*128*T_PAD];
    const int bn = blockIdx.x * 128;
    float acc[4][4][4];
#pragma unroll
    for (int mi = 0; mi < 4; mi++)
#pragma unroll
        for (int ni = 0; ni < 4; ni++)
#pragma unroll
            for (int r = 0; r < 4; r++) acc[mi][ni][r] = 0.0f;

    tile_gemm<HID>(g_h0, g_WhhInsP, 0, bn, acc, As, Bs);
    fuse_epilogue(acc, 0, bn, g_Gx + (size_t)l * KROWS * G4, (long)G4,
                  g_c0, g_Hi + (size_t)l * KROWS * HID, g_Ci + (size_t)l * KROWS * HID);
}

// ---------------- final: masked max over roots, then dot with Wlin ----------------
__global__ void final1_kernel()
{
    int b = blockIdx.x;
    int h = threadIdx.x;
    float m = -1e30f;
    for (int r = b*32; r < b*32 + 32; r++)
        if (g_appears[r] == 0) m = fmaxf(m, g_Hi[(size_t)r*HID + h]);
    g_partial[b*HID + h] = m;
}

__global__ void final2_kernel(const float* __restrict__ Wlin,
                              const float* __restrict__ blin,
                              float* __restrict__ out)
{
    int h = threadIdx.x;
    float m = -1e30f;
    for (int b = 0; b < 64; b++) m = fmaxf(m, g_partial[b*HID + h]);
    float v = m * Wlin[h];
    __shared__ float s[256];
    s[h] = v;
    __syncthreads();
    for (int st = 128; st > 0; st >>= 1) {
        if (h < st) s[h] += s[h + st];
        __syncthreads();
    }
    if (h == 0) out[0] = s[0] + blin[0];
}

// ---------------- launch ----------------
extern "C" void kernel_launch(void* const* d_in, const int* in_sizes, int n_in,
                              void* d_out, int out_size)
{
    const float* tokens   = (const float*)d_in[0];
    const int*   pidx     = (const int*)  d_in[1];
    const unsigned char* pval = (const unsigned char*)d_in[2];
    const float* Wih_tok  = (const float*)d_in[3];
    const float* Whh_tok  = (const float*)d_in[4];
    const float* bih_tok  = (const float*)d_in[5];
    const float* bhh_tok  = (const float*)d_in[6];
    const float* Wih_ins  = (const float*)d_in[7];
    const float* Whh_ins  = (const float*)d_in[8];
    const float* bih_ins  = (const float*)d_in[9];
    const float* bhh_ins  = (const float*)d_in[10];
    const float* Wlin     = (const float*)d_in[11];
    const float* blin     = (const float*)d_in[12];
    float* out = (float*)d_out;

    float *pXp, *pH, *pGx, *pWihInsP, *pBT, *pBI;
    cudaGetSymbolAddress((void**)&pXp,      g_Xp);
    cudaGetSymbolAddress((void**)&pH,       g_H);
    cudaGetSymbolAddress((void**)&pGx,      g_Gx);
    cudaGetSymbolAddress((void**)&pWihInsP, g_WihInsP);
    cudaGetSymbolAddress((void**)&pBT,      g_biasTokP);
    cudaGetSymbolAddress((void**)&pBI,      g_biasInsP);

    cudaFuncSetAttribute(phase2_kernel, cudaFuncAttributeMaxDynamicSharedMemorySize, P2_SMEM);
    cudaFuncSetAttribute(p1_f16_kernel, cudaFuncAttributeMaxDynamicSharedMemorySize, P1_SMEM);

    prep_kernel<<<1, 256>>>(pval, pidx);
    permAll_kernel<<<G4, 256>>>(Whh_tok, Whh_ins, Wih_tok, Wih_ins,
                                bih_tok, bhh_tok, bih_ins, bhh_ins);

    // Phase 1: Xp (gate-interleaved) = tokens @ WihTokH^T + biasTokP  (fp16 MMA)
    p1_f16_kernel<<<dim3(8, 256), 256, P1_SMEM>>>(tokens, pXp, pBT);

    // Phase 2: persistent token-LSTM recurrence (final hidden lands in g_H fp32)
    phase2_kernel<<<128, 256, P2_SMEM>>>();

    // Phase 3a: Gx (gate-interleaved) = ins_embed @ WihInsP^T + biasInsP (tf32)
    mma_plain_kernel<HID><<<dim3(8, 16), 256>>>(pH, pWihInsP, pGx, pBI);

    // Phase 3b: per-level gather (wide) + fused GEMM+LSTM (tf32)
    for (int l = 0; l < LEVELS; l++) {
        gather_kernel<<<KROWS, HID>>>(pidx, l);
        level_kernel<<<8, 256>>>(l);
    }

    final1_kernel<<<64, 256>>>();
    final2_kernel<<<1, 256>>>(Wlin, blin, out);
}